// round 8
// baseline (speedup 1.0000x reference)
#include <cuda_runtime.h>
#include <cuda_bf16.h>
#include <cstdint>

// Problem constants
#define B_ 256
#define T_ 512          // TM1
#define N_ 256
#define H_ 256
#define G_ 1024         // 4*H
#define ENC_OFF ((size_t)B_ * T_ * N_)   // offset of input_encoded in d_out

// ---------------- device scratch (no cudaMalloc allowed) ----------------
__device__ float g_attn[B_ * N_];                      // softmax(x_scores)
__device__ float g_G1[(size_t)T_ * B_ * G_];           // gates pre-recurrence, [m=t*B+b][j]
__device__ float g_hbuf[2][H_ * B_];                   // ping-pong hidden state, [h][b]
__device__ __nv_bfloat16 g_Ahi[(size_t)T_ * B_ * N_];  // weighted, bf16 hi
__device__ __nv_bfloat16 g_Alo[(size_t)T_ * B_ * N_];  // weighted, bf16 lo
__device__ __nv_bfloat16 g_Bhi[G_ * N_];               // W_ih, bf16 hi
__device__ __nv_bfloat16 g_Blo[G_ * N_];               // W_ih, bf16 lo

// ---------------- packed fp32x2 helpers ----------------
#define FMA2(d, a, b) asm("fma.rn.f32x2 %0, %1, %2, %0;" : "+l"(d) : "l"(a), "l"(b))

__device__ __forceinline__ unsigned long long pk2(float lo, float hi) {
    unsigned long long r;
    asm("mov.b64 %0, {%1, %2};" : "=l"(r) : "f"(lo), "f"(hi));
    return r;
}
__device__ __forceinline__ void upk2(unsigned long long v, float& lo, float& hi) {
    asm("mov.b64 {%0, %1}, %2;" : "=f"(lo), "=f"(hi) : "l"(v));
}
__device__ __forceinline__ float sigf(float x) {
    return __fdividef(1.f, 1.f + __expf(-x));
}
__device__ __forceinline__ float tanhfast(float x) {
    return __fdividef(2.f, 1.f + __expf(-2.f * x)) - 1.f;
}
__device__ __forceinline__ uint32_t smem_to_u32(const void* p) {
    uint32_t a;
    asm("{ .reg .u64 t; cvta.to.shared.u64 t, %1; cvt.u32.u64 %0, t; }" : "=r"(a) : "l"(p));
    return a;
}

// ---------------- cp.async helpers ----------------
#define CP_ASYNC16(dst, src) \
    asm volatile("cp.async.cg.shared.global [%0], [%1], 16;" :: "r"(dst), "l"(src) : "memory")
#define CP_COMMIT() asm volatile("cp.async.commit_group;" ::: "memory")
#define CP_WAIT1() asm volatile("cp.async.wait_group 1;" ::: "memory")
#define CP_WAIT0() asm volatile("cp.async.wait_group 0;" ::: "memory")

// ---------------- K1: x_scores + softmax -> attn, zero h buffer ----------------
__global__ void k_attn(const float* __restrict__ in, const float* __restrict__ attn_w) {
    __shared__ float wx[T_];
    __shared__ float red[N_];
    int b = blockIdx.x;
    int n = threadIdx.x;

    wx[n]       = attn_w[2 * H_ + n];
    wx[n + 256] = attn_w[2 * H_ + 256 + n];
    __syncthreads();

    const float* p = in + (size_t)b * T_ * N_ + n;
    float acc = 0.f;
#pragma unroll 8
    for (int t = 0; t < T_; ++t)
        acc = fmaf(p[(size_t)t * N_], wx[t], acc);

    red[n] = acc;
    __syncthreads();
    for (int s = 128; s > 0; s >>= 1) {
        if (n < s) red[n] = fmaxf(red[n], red[n + s]);
        __syncthreads();
    }
    float mx = red[0];
    __syncthreads();
    float e = expf(acc - mx);
    red[n] = e;
    __syncthreads();
    for (int s = 128; s > 0; s >>= 1) {
        if (n < s) red[n] += red[n + s];
        __syncthreads();
    }
    g_attn[b * N_ + n] = e / red[0];
    g_hbuf[0][b * N_ + n] = 0.f;
}

// ---------------- K2: weighted = attn * x -> out region 0 + bf16 hi/lo ---------
__global__ void k_weighted(const float* __restrict__ in, float* __restrict__ out) {
    int blk = blockIdx.x;            // b*T_ + t
    int b = blk >> 9;
    int t = blk & 511;
    int n = threadIdx.x;
    size_t idx = (size_t)blk * N_ + n;
    float w = g_attn[b * N_ + n] * in[idx];
    out[idx] = w;
    size_t m = (size_t)t * B_ + b;   // GEMM row index
    __nv_bfloat16 hi = __float2bfloat16(w);
    __nv_bfloat16 lo = __float2bfloat16(w - __bfloat162float(hi));
    g_Ahi[m * N_ + n] = hi;
    g_Alo[m * N_ + n] = lo;
}

// ---------------- K2b: W_ih -> bf16 hi/lo ----------------
__global__ void k_convB(const float* __restrict__ Wih) {
    int j = blockIdx.x;
    int k = threadIdx.x;
    float v = Wih[(size_t)j * N_ + k];
    __nv_bfloat16 hi = __float2bfloat16(v);
    __nv_bfloat16 lo = __float2bfloat16(v - __bfloat162float(hi));
    g_Bhi[j * N_ + k] = hi;
    g_Blo[j * N_ + k] = lo;
}

// ---------------- K3: mma.sync bf16 split GEMM, cp.async double-buffered -------
// (unchanged from round 7 — proven at 517us)
#define LDM_X4(r0, r1, r2, r3, a) \
    asm volatile("ldmatrix.sync.aligned.m8n8.x4.shared.b16 {%0,%1,%2,%3}, [%4];" \
                 : "=r"(r0), "=r"(r1), "=r"(r2), "=r"(r3) : "r"(a))
#define MMA16816(c, a, b) \
    asm volatile("mma.sync.aligned.m16n8k16.row.col.f32.bf16.bf16.f32 " \
                 "{%0,%1,%2,%3}, {%4,%5,%6,%7}, {%8,%9}, {%0,%1,%2,%3};" \
                 : "+f"((c)[0]), "+f"((c)[1]), "+f"((c)[2]), "+f"((c)[3]) \
                 : "r"((a)[0]), "r"((a)[1]), "r"((a)[2]), "r"((a)[3]), "r"((b)[0]), "r"((b)[1]))

#define TILE_BYTES 16384           // 128 x 64 bf16

__global__ void __launch_bounds__(256) k_gemm_mma(
        const float* __restrict__ b_ih, const float* __restrict__ b_hh) {
    __shared__ __align__(16) __nv_bfloat16 Sb[4 * 128 * 64];   // 64 KB
    __shared__ float bias_s[128];

    int tid = threadIdx.x;
    int wid = tid >> 5;
    int lane = tid & 31;
    int nt = blockIdx.x;             // 0..7  gate tile
    int mt = blockIdx.y;             // 0..1023 m tile
    int j0 = nt * 128;
    int wm = wid >> 2;               // 0..1
    int wn = wid & 3;                // 0..3

    if (tid < 128) bias_s[tid] = b_ih[j0 + tid] + b_hh[j0 + tid];

    uint32_t s_base = smem_to_u32(Sb);

    int st_r[4], st_sw[4];
#pragma unroll
    for (int it = 0; it < 4; ++it) {
        int idx = tid + it * 256;        // 0..1023
        int r = idx >> 3;
        int kg = idx & 7;
        st_r[it] = r * 32 + kg;
        st_sw[it] = r * 8 + (kg ^ (r & 7));
    }

    const __nv_bfloat16* a_srcs[3] = {g_Ahi, g_Alo, g_Ahi};
    const __nv_bfloat16* b_srcs[3] = {g_Bhi, g_Bhi, g_Blo};

#define ISSUE_CHUNK(ch) do { \
        int _term = (ch) >> 2; \
        int _kk0 = ((ch) & 3) * 64; \
        const char* _gA = (const char*)(a_srcs[_term] + (size_t)mt * 128 * N_ + _kk0); \
        const char* _gB = (const char*)(b_srcs[_term] + (size_t)j0 * N_ + _kk0); \
        uint32_t _sa = s_base + ((ch) & 1) * 2u * TILE_BYTES; \
        uint32_t _sb = _sa + TILE_BYTES; \
        _Pragma("unroll") \
        for (int _it = 0; _it < 4; ++_it) { \
            CP_ASYNC16(_sa + (uint32_t)st_sw[_it] * 16u, _gA + (size_t)st_r[_it] * 16); \
            CP_ASYNC16(_sb + (uint32_t)st_sw[_it] * 16u, _gB + (size_t)st_r[_it] * 16); \
        } \
        CP_COMMIT(); \
    } while (0)

    int a_r15 = lane & 15;
    int a_kh  = lane >> 4;
    int b_row = ((lane & 16) >> 1) + (lane & 7);
    int b_kh  = (lane >> 3) & 1;

    float acc[4][4][4];
#pragma unroll
    for (int i = 0; i < 4; ++i)
#pragma unroll
        for (int j = 0; j < 4; ++j)
#pragma unroll
            for (int q = 0; q < 4; ++q) acc[i][j][q] = 0.f;

    ISSUE_CHUNK(0);

    for (int ch = 0; ch < 12; ++ch) {
        if (ch + 1 < 12) {
            ISSUE_CHUNK(ch + 1);
            CP_WAIT1();
        } else {
            CP_WAIT0();
        }
        __syncthreads();

        uint32_t as_base = s_base + (ch & 1) * 2u * TILE_BYTES;
        uint32_t bs_base = as_base + TILE_BYTES;

#pragma unroll
        for (int ks = 0; ks < 4; ++ks) {
            uint32_t afr[4][4];
            uint32_t bfr[4][2];
#pragma unroll
            for (int tm = 0; tm < 4; ++tm) {
                int row = wm * 64 + tm * 16 + a_r15;
                int c = (2 * ks + a_kh) ^ (a_r15 & 7);
                uint32_t addr = as_base + (uint32_t)(row * 64 + c * 8) * 2u;
                LDM_X4(afr[tm][0], afr[tm][1], afr[tm][2], afr[tm][3], addr);
            }
#pragma unroll
            for (int tn2 = 0; tn2 < 2; ++tn2) {
                int row = wn * 32 + tn2 * 16 + b_row;
                int c = (2 * ks + b_kh) ^ (b_row & 7);
                uint32_t addr = bs_base + (uint32_t)(row * 64 + c * 8) * 2u;
                uint32_t r0, r1, r2, r3;
                LDM_X4(r0, r1, r2, r3, addr);
                bfr[tn2 * 2 + 0][0] = r0; bfr[tn2 * 2 + 0][1] = r1;
                bfr[tn2 * 2 + 1][0] = r2; bfr[tn2 * 2 + 1][1] = r3;
            }
#pragma unroll
            for (int tm = 0; tm < 4; ++tm)
#pragma unroll
                for (int tn = 0; tn < 4; ++tn)
                    MMA16816(acc[tm][tn], afr[tm], bfr[tn]);
        }
        __syncthreads();
    }

    int qr = lane >> 2;
    int qc = (lane & 3) * 2;
#pragma unroll
    for (int tm = 0; tm < 4; ++tm) {
#pragma unroll
        for (int tn = 0; tn < 4; ++tn) {
            int colt = wn * 32 + tn * 8 + qc;
            size_t m0 = (size_t)mt * 128 + wm * 64 + tm * 16 + qr;
            float bx = bias_s[colt], by = bias_s[colt + 1];
            float2 v0 = make_float2(acc[tm][tn][0] + bx, acc[tm][tn][1] + by);
            float2 v1 = make_float2(acc[tm][tn][2] + bx, acc[tm][tn][3] + by);
            *(float2*)(g_G1 + m0 * G_ + j0 + colt) = v0;
            *(float2*)(g_G1 + (m0 + 8) * G_ + j0 + colt) = v1;
        }
    }
}

// ---------------- K4: persistent recurrence, HW cluster barrier ----------------
// Retiled: CTA = 16 batches x 32 hid. grid = (8 hid-tiles, 16 batch-groups).
// Cluster (8,1,1) = the 8 hid-tile CTAs of one batch group: the ONLY CTAs that
// must exchange h. barrier.cluster.arrive (release) / .wait (acquire) replaces
// the software global barrier; batch groups drift freely (disjoint state).
// SMEM: Ws [256k][32hid][4q] fp32 = 128KB (resident); Hs [256k][16b dup] = 32KB.
__global__ void __launch_bounds__(128, 1) __cluster_dims__(8, 1, 1) k_recur(
        const float* __restrict__ Whh, float* __restrict__ out_enc) {
    extern __shared__ float sm[];
    float* Ws = sm;                   // 32768 floats (128 KB)
    float* Hs = sm + 32768;           // 8192 floats  (32 KB, duplicated h)
    const ulonglong2* Ws2 = (const ulonglong2*)Ws;
    const ulonglong2* Hs2 = (const ulonglong2*)Hs;
    float4* Hs4 = (float4*)Hs;

    int tid = threadIdx.x;            // 128
    int h0  = blockIdx.x * 32;        // hid tile (cluster dimension)
    int b0  = blockIdx.y * 16;        // batch group

    // Load W_hh tile once; resident across all 512 steps. layout [k][hid(32)][q(4)]
    for (int idx = tid; idx < 32768; idx += 128) {
        int k = idx >> 7;
        int col = idx & 127;
        int hh = col >> 2;
        int q = col & 3;
        Ws[idx] = Whh[(size_t)(q * H_ + h0 + hh) * N_ + k];
    }

    int hid = tid & 31;               // 0..31
    int bg  = tid >> 5;               // 0..3
    float creg[4] = {0.f, 0.f, 0.f, 0.f};
    __syncthreads();

    // prefetch acc for t=0
    unsigned long long accA[4], accB[4];   // (i,f) and (g,o) gate pairs
#pragma unroll
    for (int i = 0; i < 4; ++i) {
        int b = b0 + bg * 4 + i;
        const float* g1 = g_G1 + ((size_t)b) * G_ + h0 + hid;
        accA[i] = pk2(__ldcg(g1 + 0),   __ldcg(g1 + 256));
        accB[i] = pk2(__ldcg(g1 + 512), __ldcg(g1 + 768));
    }

    for (int t = 0; t < T_; ++t) {
        // stage this CTA's h slice [256 k][16 b] DUPLICATED for FMA2 (32 KB)
        const float4* gh4 = (const float4*)g_hbuf[t & 1];
#pragma unroll
        for (int it = 0; it < 8; ++it) {
            int idx = tid + it * 128;         // 0..1023
            int k = idx >> 2;
            int j = idx & 3;
            float4 v = __ldcg(gh4 + k * 64 + (b0 >> 2) + j);
            Hs4[k * 8 + j * 2]     = make_float4(v.x, v.x, v.y, v.y);
            Hs4[k * 8 + j * 2 + 1] = make_float4(v.z, v.z, v.w, v.w);
        }
        __syncthreads();

        // gates += h @ W_hh^T   (3 LDS.128 + 8 FMA2 per k — proven pattern)
        const ulonglong2* wp = Ws2 + hid;
        const ulonglong2* hp = Hs2 + bg * 2;
#pragma unroll 8
        for (int k = 0; k < 256; ++k) {
            ulonglong2 w   = wp[k * 32];      // (w_i,w_f),(w_g,w_o)
            ulonglong2 h01 = hp[k * 8];       // (h0,h0),(h1,h1)
            ulonglong2 h23 = hp[k * 8 + 1];   // (h2,h2),(h3,h3)
            FMA2(accA[0], h01.x, w.x); FMA2(accB[0], h01.x, w.y);
            FMA2(accA[1], h01.y, w.x); FMA2(accB[1], h01.y, w.y);
            FMA2(accA[2], h23.x, w.x); FMA2(accB[2], h23.x, w.y);
            FMA2(accA[3], h23.y, w.x); FMA2(accB[3], h23.y, w.y);
        }

        // fused LSTM cell update + output store
        float* ghw = g_hbuf[(t + 1) & 1];
#pragma unroll
        for (int i = 0; i < 4; ++i) {
            int b = b0 + bg * 4 + i;
            float gi, gf, gg, go;
            upk2(accA[i], gi, gf);
            upk2(accB[i], gg, go);
            float ig = sigf(gi);
            float fg = sigf(gf);
            float g_ = tanhfast(gg);
            float og = sigf(go);
            float c = fmaf(fg, creg[i], ig * g_);
            creg[i] = c;
            float hn = og * tanhfast(c);
            __stcg(&ghw[(h0 + hid) * B_ + b], hn);
            out_enc[((size_t)b * T_ + t) * H_ + h0 + hid] = hn;
        }

        if (t + 1 < T_) {
            // release our h stores to cluster peers
            asm volatile("barrier.cluster.arrive.aligned;" ::: "memory");
            // prefetch acc for step t+1 in the barrier gap (G1 is static)
#pragma unroll
            for (int i = 0; i < 4; ++i) {
                int b = b0 + bg * 4 + i;
                const float* g1 = g_G1 + ((size_t)(t + 1) * B_ + b) * G_ + h0 + hid;
                accA[i] = pk2(__ldcg(g1 + 0),   __ldcg(g1 + 256));
                accB[i] = pk2(__ldcg(g1 + 512), __ldcg(g1 + 768));
            }
            asm volatile("barrier.cluster.wait.aligned;" ::: "memory");
        }
    }
}

// ---------------- launch ----------------
extern "C" void kernel_launch(void* const* d_in, const int* in_sizes, int n_in,
                              void* d_out, int out_size) {
    const float* input  = (const float*)d_in[0];
    const float* W_ih   = (const float*)d_in[1];
    const float* W_hh   = (const float*)d_in[2];
    const float* b_ih   = (const float*)d_in[3];
    const float* b_hh   = (const float*)d_in[4];
    const float* attn_w = (const float*)d_in[5];
    float* out = (float*)d_out;

    cudaFuncSetAttribute(k_recur, cudaFuncAttributeMaxDynamicSharedMemorySize, 163840);

    // K1: attention weights (+ zero h state)
    k_attn<<<B_, N_>>>(input, attn_w);
    // K2: weighted input -> output region 0 + bf16 hi/lo staging
    k_weighted<<<B_ * T_, N_>>>(input, out);
    // K2b: W_ih bf16 hi/lo
    k_convB<<<G_, N_>>>(W_ih);
    // K3: HMMA split-bf16 GEMM into g_G1, cp.async double-buffered
    dim3 g3(8, 1024);
    k_gemm_mma<<<g3, 256>>>(b_ih, b_hh);
    // K4: persistent recurrence -> output region 1 (HW cluster barrier)
    dim3 g4(8, 16);
    k_recur<<<g4, 128, 163840>>>(W_hh, out + ENC_OFF);
}

// round 9
// speedup vs baseline: 1.2195x; 1.2195x over previous
#include <cuda_runtime.h>
#include <cuda_bf16.h>
#include <cstdint>

// Problem constants
#define B_ 256
#define T_ 512          // TM1
#define N_ 256
#define H_ 256
#define G_ 1024         // 4*H
#define ENC_OFF ((size_t)B_ * T_ * N_)   // offset of input_encoded in d_out

// ---------------- device scratch (no cudaMalloc allowed) ----------------
__device__ float g_attn[B_ * N_];                      // softmax(x_scores)
__device__ float g_G1[(size_t)T_ * B_ * G_];           // gates pre-recurrence, [m=t*B+b][j]
__device__ float g_hbuf[2][H_ * B_];                   // ping-pong hidden state, [h][b]
__device__ __nv_bfloat16 g_Ahi[(size_t)T_ * B_ * N_];  // weighted, bf16 hi
__device__ __nv_bfloat16 g_Alo[(size_t)T_ * B_ * N_];  // weighted, bf16 lo
__device__ __nv_bfloat16 g_Bhi[G_ * N_];               // W_ih, bf16 hi
__device__ __nv_bfloat16 g_Blo[G_ * N_];               // W_ih, bf16 lo
__device__ unsigned g_cnt_leaf[8];                     // tree barrier leaves
__device__ unsigned g_cnt_root;                        // tree barrier root
__device__ volatile unsigned g_gen;                    // global generation

// ---------------- packed fp32x2 helpers ----------------
#define FMA2(d, a, b) asm("fma.rn.f32x2 %0, %1, %2, %0;" : "+l"(d) : "l"(a), "l"(b))

__device__ __forceinline__ unsigned long long pk2(float lo, float hi) {
    unsigned long long r;
    asm("mov.b64 %0, {%1, %2};" : "=l"(r) : "f"(lo), "f"(hi));
    return r;
}
__device__ __forceinline__ void upk2(unsigned long long v, float& lo, float& hi) {
    asm("mov.b64 {%0, %1}, %2;" : "=f"(lo), "=f"(hi) : "l"(v));
}
__device__ __forceinline__ float sigf(float x) {
    return __fdividef(1.f, 1.f + __expf(-x));
}
__device__ __forceinline__ float tanhfast(float x) {
    return __fdividef(2.f, 1.f + __expf(-2.f * x)) - 1.f;
}
__device__ __forceinline__ uint32_t smem_to_u32(const void* p) {
    uint32_t a;
    asm("{ .reg .u64 t; cvta.to.shared.u64 t, %1; cvt.u32.u64 %0, t; }" : "=r"(a) : "l"(p));
    return a;
}

// ---------------- cp.async helpers ----------------
#define CP_ASYNC16(dst, src) \
    asm volatile("cp.async.cg.shared.global [%0], [%1], 16;" :: "r"(dst), "l"(src) : "memory")
#define CP_COMMIT() asm volatile("cp.async.commit_group;" ::: "memory")
#define CP_WAIT1() asm volatile("cp.async.wait_group 1;" ::: "memory")
#define CP_WAIT0() asm volatile("cp.async.wait_group 0;" ::: "memory")

// ---------------- K1: x_scores + softmax -> attn, zero h buffer ----------------
__global__ void k_attn(const float* __restrict__ in, const float* __restrict__ attn_w) {
    __shared__ float wx[T_];
    __shared__ float red[N_];
    int b = blockIdx.x;
    int n = threadIdx.x;

    wx[n]       = attn_w[2 * H_ + n];
    wx[n + 256] = attn_w[2 * H_ + 256 + n];
    __syncthreads();

    const float* p = in + (size_t)b * T_ * N_ + n;
    float acc = 0.f;
#pragma unroll 8
    for (int t = 0; t < T_; ++t)
        acc = fmaf(p[(size_t)t * N_], wx[t], acc);

    red[n] = acc;
    __syncthreads();
    for (int s = 128; s > 0; s >>= 1) {
        if (n < s) red[n] = fmaxf(red[n], red[n + s]);
        __syncthreads();
    }
    float mx = red[0];
    __syncthreads();
    float e = expf(acc - mx);
    red[n] = e;
    __syncthreads();
    for (int s = 128; s > 0; s >>= 1) {
        if (n < s) red[n] += red[n + s];
        __syncthreads();
    }
    g_attn[b * N_ + n] = e / red[0];
    g_hbuf[0][b * N_ + n] = 0.f;
}

// ---------------- K2: weighted = attn * x -> out region 0 + bf16 hi/lo ---------
__global__ void k_weighted(const float* __restrict__ in, float* __restrict__ out) {
    int blk = blockIdx.x;            // b*T_ + t
    int b = blk >> 9;
    int t = blk & 511;
    int n = threadIdx.x;
    size_t idx = (size_t)blk * N_ + n;
    float w = g_attn[b * N_ + n] * in[idx];
    out[idx] = w;
    size_t m = (size_t)t * B_ + b;   // GEMM row index
    __nv_bfloat16 hi = __float2bfloat16(w);
    __nv_bfloat16 lo = __float2bfloat16(w - __bfloat162float(hi));
    g_Ahi[m * N_ + n] = hi;
    g_Alo[m * N_ + n] = lo;
}

// ---------------- K2b: W_ih -> bf16 hi/lo ----------------
__global__ void k_convB(const float* __restrict__ Wih) {
    int j = blockIdx.x;
    int k = threadIdx.x;
    float v = Wih[(size_t)j * N_ + k];
    __nv_bfloat16 hi = __float2bfloat16(v);
    __nv_bfloat16 lo = __float2bfloat16(v - __bfloat162float(hi));
    g_Bhi[j * N_ + k] = hi;
    g_Blo[j * N_ + k] = lo;
}

// ---------------- K3: mma.sync bf16 split GEMM, cp.async double-buffered -------
// (unchanged — proven at 517us)
#define LDM_X4(r0, r1, r2, r3, a) \
    asm volatile("ldmatrix.sync.aligned.m8n8.x4.shared.b16 {%0,%1,%2,%3}, [%4];" \
                 : "=r"(r0), "=r"(r1), "=r"(r2), "=r"(r3) : "r"(a))
#define MMA16816(c, a, b) \
    asm volatile("mma.sync.aligned.m16n8k16.row.col.f32.bf16.bf16.f32 " \
                 "{%0,%1,%2,%3}, {%4,%5,%6,%7}, {%8,%9}, {%0,%1,%2,%3};" \
                 : "+f"((c)[0]), "+f"((c)[1]), "+f"((c)[2]), "+f"((c)[3]) \
                 : "r"((a)[0]), "r"((a)[1]), "r"((a)[2]), "r"((a)[3]), "r"((b)[0]), "r"((b)[1]))

#define TILE_BYTES 16384           // 128 x 64 bf16

__global__ void __launch_bounds__(256) k_gemm_mma(
        const float* __restrict__ b_ih, const float* __restrict__ b_hh) {
    __shared__ __align__(16) __nv_bfloat16 Sb[4 * 128 * 64];   // 64 KB
    __shared__ float bias_s[128];

    int tid = threadIdx.x;
    int wid = tid >> 5;
    int lane = tid & 31;
    int nt = blockIdx.x;             // 0..7  gate tile
    int mt = blockIdx.y;             // 0..1023 m tile
    int j0 = nt * 128;
    int wm = wid >> 2;               // 0..1
    int wn = wid & 3;                // 0..3

    if (tid < 128) bias_s[tid] = b_ih[j0 + tid] + b_hh[j0 + tid];

    uint32_t s_base = smem_to_u32(Sb);

    int st_r[4], st_sw[4];
#pragma unroll
    for (int it = 0; it < 4; ++it) {
        int idx = tid + it * 256;        // 0..1023
        int r = idx >> 3;
        int kg = idx & 7;
        st_r[it] = r * 32 + kg;
        st_sw[it] = r * 8 + (kg ^ (r & 7));
    }

    const __nv_bfloat16* a_srcs[3] = {g_Ahi, g_Alo, g_Ahi};
    const __nv_bfloat16* b_srcs[3] = {g_Bhi, g_Bhi, g_Blo};

#define ISSUE_CHUNK(ch) do { \
        int _term = (ch) >> 2; \
        int _kk0 = ((ch) & 3) * 64; \
        const char* _gA = (const char*)(a_srcs[_term] + (size_t)mt * 128 * N_ + _kk0); \
        const char* _gB = (const char*)(b_srcs[_term] + (size_t)j0 * N_ + _kk0); \
        uint32_t _sa = s_base + ((ch) & 1) * 2u * TILE_BYTES; \
        uint32_t _sb = _sa + TILE_BYTES; \
        _Pragma("unroll") \
        for (int _it = 0; _it < 4; ++_it) { \
            CP_ASYNC16(_sa + (uint32_t)st_sw[_it] * 16u, _gA + (size_t)st_r[_it] * 16); \
            CP_ASYNC16(_sb + (uint32_t)st_sw[_it] * 16u, _gB + (size_t)st_r[_it] * 16); \
        } \
        CP_COMMIT(); \
    } while (0)

    int a_r15 = lane & 15;
    int a_kh  = lane >> 4;
    int b_row = ((lane & 16) >> 1) + (lane & 7);
    int b_kh  = (lane >> 3) & 1;

    float acc[4][4][4];
#pragma unroll
    for (int i = 0; i < 4; ++i)
#pragma unroll
        for (int j = 0; j < 4; ++j)
#pragma unroll
            for (int q = 0; q < 4; ++q) acc[i][j][q] = 0.f;

    ISSUE_CHUNK(0);

    for (int ch = 0; ch < 12; ++ch) {
        if (ch + 1 < 12) {
            ISSUE_CHUNK(ch + 1);
            CP_WAIT1();
        } else {
            CP_WAIT0();
        }
        __syncthreads();

        uint32_t as_base = s_base + (ch & 1) * 2u * TILE_BYTES;
        uint32_t bs_base = as_base + TILE_BYTES;

#pragma unroll
        for (int ks = 0; ks < 4; ++ks) {
            uint32_t afr[4][4];
            uint32_t bfr[4][2];
#pragma unroll
            for (int tm = 0; tm < 4; ++tm) {
                int row = wm * 64 + tm * 16 + a_r15;
                int c = (2 * ks + a_kh) ^ (a_r15 & 7);
                uint32_t addr = as_base + (uint32_t)(row * 64 + c * 8) * 2u;
                LDM_X4(afr[tm][0], afr[tm][1], afr[tm][2], afr[tm][3], addr);
            }
#pragma unroll
            for (int tn2 = 0; tn2 < 2; ++tn2) {
                int row = wn * 32 + tn2 * 16 + b_row;
                int c = (2 * ks + b_kh) ^ (b_row & 7);
                uint32_t addr = bs_base + (uint32_t)(row * 64 + c * 8) * 2u;
                uint32_t r0, r1, r2, r3;
                LDM_X4(r0, r1, r2, r3, addr);
                bfr[tn2 * 2 + 0][0] = r0; bfr[tn2 * 2 + 0][1] = r1;
                bfr[tn2 * 2 + 1][0] = r2; bfr[tn2 * 2 + 1][1] = r3;
            }
#pragma unroll
            for (int tm = 0; tm < 4; ++tm)
#pragma unroll
                for (int tn = 0; tn < 4; ++tn)
                    MMA16816(acc[tm][tn], afr[tm], bfr[tn]);
        }
        __syncthreads();
    }

    int qr = lane >> 2;
    int qc = (lane & 3) * 2;
#pragma unroll
    for (int tm = 0; tm < 4; ++tm) {
#pragma unroll
        for (int tn = 0; tn < 4; ++tn) {
            int colt = wn * 32 + tn * 8 + qc;
            size_t m0 = (size_t)mt * 128 + wm * 64 + tm * 16 + qr;
            float bx = bias_s[colt], by = bias_s[colt + 1];
            float2 v0 = make_float2(acc[tm][tn][0] + bx, acc[tm][tn][1] + by);
            float2 v1 = make_float2(acc[tm][tn][2] + bx, acc[tm][tn][3] + by);
            *(float2*)(g_G1 + m0 * G_ + j0 + colt) = v0;
            *(float2*)(g_G1 + (m0 + 8) * G_ + j0 + colt) = v1;
        }
    }
}

// ---------------- K4: persistent recurrence ----------------
// Tree barrier with GLOBAL semantics (proven R7): 8 leaves x 16 -> root x 8 -> gen.
__device__ __forceinline__ void grid_sync_tree(int leaf) {
    __threadfence();
    __syncthreads();
    if (threadIdx.x == 0) {
        unsigned gen = g_gen;
        if (atomicAdd(&g_cnt_leaf[leaf], 1u) == 15u) {
            g_cnt_leaf[leaf] = 0;
            if (atomicAdd(&g_cnt_root, 1u) == 7u) {
                g_cnt_root = 0;
                __threadfence();
                g_gen = gen + 1u;
            }
        }
        while (g_gen == gen) { __nanosleep(64); }
        __threadfence();
    }
    __syncthreads();
}

// grid (8, 16): blockIdx.x -> 32-batch tile, blockIdx.y -> 16-hidden tile.
// 256 threads (2 warps/SMSP for latency hiding). Thread = (bg 0..15, hid 0..15),
// 2 batches x 4 gates: per k just 2 LDS.128 + 4 FMA2.
__global__ void __launch_bounds__(256, 1) k_recur(
        const float* __restrict__ Whh, float* __restrict__ out_enc) {
    extern __shared__ float sm[];
    float* Ws = sm;                   // 16384 floats (64 KB): [k][hid16][q4]
    float* Hs = sm + 16384;           // 16384 floats (64 KB): [k][32 b duplicated]
    const ulonglong2* Ws2 = (const ulonglong2*)Ws;
    const ulonglong2* Hs2 = (const ulonglong2*)Hs;
    float4* Hs4 = (float4*)Hs;

    int tid = threadIdx.x;            // 256
    int b0  = blockIdx.x * 32;
    int h0  = blockIdx.y * 16;
    int leaf = blockIdx.x;

    for (int idx = tid; idx < 16384; idx += 256) {
        int k = idx >> 6;
        int col = idx & 63;
        int hh = col >> 2;
        int q = col & 3;
        Ws[idx] = Whh[(size_t)(q * H_ + h0 + hh) * N_ + k];
    }

    int bg  = tid >> 4;               // 0..15  (2 batches each)
    int hid = tid & 15;               // 0..15
    float creg[2] = {0.f, 0.f};
    __syncthreads();

    // prefetch acc for t=0
    unsigned long long accA[2], accB[2];   // (i,f) and (g,o) gate pairs, 2 batches
#pragma unroll
    for (int i = 0; i < 2; ++i) {
        int b = b0 + bg * 2 + i;
        const float* g1 = g_G1 + ((size_t)b) * G_ + h0 + hid;
        accA[i] = pk2(__ldcg(g1 + 0),   __ldcg(g1 + 256));
        accB[i] = pk2(__ldcg(g1 + 512), __ldcg(g1 + 768));
    }

    for (int t = 0; t < T_; ++t) {
        // stage this CTA's h slice [256 k][32 b] DUPLICATED for FMA2
        const float4* gh4 = (const float4*)g_hbuf[t & 1];
#pragma unroll
        for (int it = 0; it < 8; ++it) {
            int idx = tid + it * 256;         // 0..2047
            int k = idx >> 3;
            int j = idx & 7;
            float4 v = __ldcg(gh4 + k * 64 + (b0 >> 2) + j);
            Hs4[k * 16 + j * 2]     = make_float4(v.x, v.x, v.y, v.y);
            Hs4[k * 16 + j * 2 + 1] = make_float4(v.z, v.z, v.w, v.w);
        }
        __syncthreads();

        // gates += h @ W_hh^T   (2 LDS.128 + 4 FMA2 per k)
        const ulonglong2* wp = Ws2 + hid;
        const ulonglong2* hp = Hs2 + bg;
#pragma unroll 8
        for (int k = 0; k < 256; ++k) {
            ulonglong2 w = wp[k * 16];        // (w_i,w_f),(w_g,w_o)
            ulonglong2 h = hp[k * 16];        // (h0,h0),(h1,h1)
            FMA2(accA[0], h.x, w.x); FMA2(accB[0], h.x, w.y);
            FMA2(accA[1], h.y, w.x); FMA2(accB[1], h.y, w.y);
        }

        // fused LSTM cell update + output store
        float* ghw = g_hbuf[(t + 1) & 1];
#pragma unroll
        for (int i = 0; i < 2; ++i) {
            int b = b0 + bg * 2 + i;
            float gi, gf, gg, go;
            upk2(accA[i], gi, gf);
            upk2(accB[i], gg, go);
            float ig = sigf(gi);
            float fg = sigf(gf);
            float g_ = tanhfast(gg);
            float og = sigf(go);
            float c = fmaf(fg, creg[i], ig * g_);
            creg[i] = c;
            float hn = og * tanhfast(c);
            __stcg(&ghw[(h0 + hid) * B_ + b], hn);
            out_enc[((size_t)b * T_ + t) * H_ + h0 + hid] = hn;
        }

        if (t + 1 < T_) {
            // prefetch acc for step t+1 BEFORE the barrier (hides DRAM latency)
#pragma unroll
            for (int i = 0; i < 2; ++i) {
                int b = b0 + bg * 2 + i;
                const float* g1 = g_G1 + ((size_t)(t + 1) * B_ + b) * G_ + h0 + hid;
                accA[i] = pk2(__ldcg(g1 + 0),   __ldcg(g1 + 256));
                accB[i] = pk2(__ldcg(g1 + 512), __ldcg(g1 + 768));
            }
            grid_sync_tree(leaf);
        }
    }
}

// ---------------- launch ----------------
extern "C" void kernel_launch(void* const* d_in, const int* in_sizes, int n_in,
                              void* d_out, int out_size) {
    const float* input  = (const float*)d_in[0];
    const float* W_ih   = (const float*)d_in[1];
    const float* W_hh   = (const float*)d_in[2];
    const float* b_ih   = (const float*)d_in[3];
    const float* b_hh   = (const float*)d_in[4];
    const float* attn_w = (const float*)d_in[5];
    float* out = (float*)d_out;

    cudaFuncSetAttribute(k_recur, cudaFuncAttributeMaxDynamicSharedMemorySize, 131072);

    // K1: attention weights (+ zero h state)
    k_attn<<<B_, N_>>>(input, attn_w);
    // K2: weighted input -> output region 0 + bf16 hi/lo staging
    k_weighted<<<B_ * T_, N_>>>(input, out);
    // K2b: W_ih bf16 hi/lo
    k_convB<<<G_, N_>>>(W_ih);
    // K3: HMMA split-bf16 GEMM into g_G1, cp.async double-buffered
    dim3 g3(8, 1024);
    k_gemm_mma<<<g3, 256>>>(b_ih, b_hh);
    // K4: persistent recurrence -> output region 1 (tree barrier, 2 warps/SMSP)
    dim3 g4(8, 16);
    k_recur<<<g4, 256, 131072>>>(W_hh, out + ENC_OFF);
}

// round 10
// speedup vs baseline: 1.4119x; 1.1578x over previous
#include <cuda_runtime.h>
#include <cuda_bf16.h>
#include <cstdint>

// Problem constants
#define B_ 256
#define T_ 512          // TM1
#define N_ 256
#define H_ 256
#define G_ 1024         // 4*H
#define ENC_OFF ((size_t)B_ * T_ * N_)   // offset of input_encoded in d_out

// ---------------- device scratch (no cudaMalloc allowed) ----------------
__device__ float g_attn[B_ * N_];                      // softmax(x_scores)
__device__ float g_G1[(size_t)T_ * B_ * G_];           // gates pre-recurrence, [m=t*B+b][j]
__device__ float g_hbuf[2][H_ * B_];                   // ping-pong hidden state, [h][b]
__device__ __nv_bfloat16 g_Ahi[(size_t)T_ * B_ * N_];  // weighted, bf16 hi
__device__ __nv_bfloat16 g_Alo[(size_t)T_ * B_ * N_];  // weighted, bf16 lo
__device__ __nv_bfloat16 g_Bhi[G_ * N_];               // W_ih, bf16 hi
__device__ __nv_bfloat16 g_Blo[G_ * N_];               // W_ih, bf16 lo
__device__ unsigned g_cnt_leaf[8];                     // tree barrier leaves
__device__ unsigned g_cnt_root;                        // tree barrier root
__device__ volatile unsigned g_gen;                    // global generation

// ---------------- packed fp32x2 helpers ----------------
#define FMA2(d, a, b) asm("fma.rn.f32x2 %0, %1, %2, %0;" : "+l"(d) : "l"(a), "l"(b))

__device__ __forceinline__ unsigned long long pk2(float lo, float hi) {
    unsigned long long r;
    asm("mov.b64 %0, {%1, %2};" : "=l"(r) : "f"(lo), "f"(hi));
    return r;
}
__device__ __forceinline__ void upk2(unsigned long long v, float& lo, float& hi) {
    asm("mov.b64 {%0, %1}, %2;" : "=f"(lo), "=f"(hi) : "l"(v));
}
__device__ __forceinline__ unsigned long long addf2(unsigned long long a, unsigned long long b) {
    unsigned long long r;
    asm("add.rn.f32x2 %0, %1, %2;" : "=l"(r) : "l"(a), "l"(b));
    return r;
}
__device__ __forceinline__ float sigf(float x) {
    return __fdividef(1.f, 1.f + __expf(-x));
}
__device__ __forceinline__ float tanhfast(float x) {
    return __fdividef(2.f, 1.f + __expf(-2.f * x)) - 1.f;
}
__device__ __forceinline__ uint32_t smem_to_u32(const void* p) {
    uint32_t a;
    asm("{ .reg .u64 t; cvta.to.shared.u64 t, %1; cvt.u32.u64 %0, t; }" : "=r"(a) : "l"(p));
    return a;
}

// ---------------- cp.async helpers ----------------
#define CP_ASYNC16(dst, src) \
    asm volatile("cp.async.cg.shared.global [%0], [%1], 16;" :: "r"(dst), "l"(src) : "memory")
#define CP_COMMIT() asm volatile("cp.async.commit_group;" ::: "memory")
#define CP_WAIT1() asm volatile("cp.async.wait_group 1;" ::: "memory")
#define CP_WAIT0() asm volatile("cp.async.wait_group 0;" ::: "memory")

// ---------------- K1: x_scores + softmax -> attn, zero h buffer ----------------
__global__ void k_attn(const float* __restrict__ in, const float* __restrict__ attn_w) {
    __shared__ float wx[T_];
    __shared__ float red[N_];
    int b = blockIdx.x;
    int n = threadIdx.x;

    wx[n]       = attn_w[2 * H_ + n];
    wx[n + 256] = attn_w[2 * H_ + 256 + n];
    __syncthreads();

    const float* p = in + (size_t)b * T_ * N_ + n;
    float acc = 0.f;
#pragma unroll 8
    for (int t = 0; t < T_; ++t)
        acc = fmaf(p[(size_t)t * N_], wx[t], acc);

    red[n] = acc;
    __syncthreads();
    for (int s = 128; s > 0; s >>= 1) {
        if (n < s) red[n] = fmaxf(red[n], red[n + s]);
        __syncthreads();
    }
    float mx = red[0];
    __syncthreads();
    float e = expf(acc - mx);
    red[n] = e;
    __syncthreads();
    for (int s = 128; s > 0; s >>= 1) {
        if (n < s) red[n] += red[n + s];
        __syncthreads();
    }
    g_attn[b * N_ + n] = e / red[0];
    g_hbuf[0][b * N_ + n] = 0.f;
}

// ---------------- K2: weighted = attn * x -> out region 0 + bf16 hi/lo ---------
__global__ void k_weighted(const float* __restrict__ in, float* __restrict__ out) {
    int blk = blockIdx.x;            // b*T_ + t
    int b = blk >> 9;
    int t = blk & 511;
    int n = threadIdx.x;
    size_t idx = (size_t)blk * N_ + n;
    float w = g_attn[b * N_ + n] * in[idx];
    out[idx] = w;
    size_t m = (size_t)t * B_ + b;   // GEMM row index
    __nv_bfloat16 hi = __float2bfloat16(w);
    __nv_bfloat16 lo = __float2bfloat16(w - __bfloat162float(hi));
    g_Ahi[m * N_ + n] = hi;
    g_Alo[m * N_ + n] = lo;
}

// ---------------- K2b: W_ih -> bf16 hi/lo ----------------
__global__ void k_convB(const float* __restrict__ Wih) {
    int j = blockIdx.x;
    int k = threadIdx.x;
    float v = Wih[(size_t)j * N_ + k];
    __nv_bfloat16 hi = __float2bfloat16(v);
    __nv_bfloat16 lo = __float2bfloat16(v - __bfloat162float(hi));
    g_Bhi[j * N_ + k] = hi;
    g_Blo[j * N_ + k] = lo;
}

// ---------------- K3: mma.sync bf16 split GEMM, cp.async double-buffered -------
// (unchanged — proven at 517us)
#define LDM_X4(r0, r1, r2, r3, a) \
    asm volatile("ldmatrix.sync.aligned.m8n8.x4.shared.b16 {%0,%1,%2,%3}, [%4];" \
                 : "=r"(r0), "=r"(r1), "=r"(r2), "=r"(r3) : "r"(a))
#define MMA16816(c, a, b) \
    asm volatile("mma.sync.aligned.m16n8k16.row.col.f32.bf16.bf16.f32 " \
                 "{%0,%1,%2,%3}, {%4,%5,%6,%7}, {%8,%9}, {%0,%1,%2,%3};" \
                 : "+f"((c)[0]), "+f"((c)[1]), "+f"((c)[2]), "+f"((c)[3]) \
                 : "r"((a)[0]), "r"((a)[1]), "r"((a)[2]), "r"((a)[3]), "r"((b)[0]), "r"((b)[1]))

#define TILE_BYTES 16384           // 128 x 64 bf16

__global__ void __launch_bounds__(256) k_gemm_mma(
        const float* __restrict__ b_ih, const float* __restrict__ b_hh) {
    __shared__ __align__(16) __nv_bfloat16 Sb[4 * 128 * 64];   // 64 KB
    __shared__ float bias_s[128];

    int tid = threadIdx.x;
    int wid = tid >> 5;
    int lane = tid & 31;
    int nt = blockIdx.x;             // 0..7  gate tile
    int mt = blockIdx.y;             // 0..1023 m tile
    int j0 = nt * 128;
    int wm = wid >> 2;               // 0..1
    int wn = wid & 3;                // 0..3

    if (tid < 128) bias_s[tid] = b_ih[j0 + tid] + b_hh[j0 + tid];

    uint32_t s_base = smem_to_u32(Sb);

    int st_r[4], st_sw[4];
#pragma unroll
    for (int it = 0; it < 4; ++it) {
        int idx = tid + it * 256;        // 0..1023
        int r = idx >> 3;
        int kg = idx & 7;
        st_r[it] = r * 32 + kg;
        st_sw[it] = r * 8 + (kg ^ (r & 7));
    }

    const __nv_bfloat16* a_srcs[3] = {g_Ahi, g_Alo, g_Ahi};
    const __nv_bfloat16* b_srcs[3] = {g_Bhi, g_Bhi, g_Blo};

#define ISSUE_CHUNK(ch) do { \
        int _term = (ch) >> 2; \
        int _kk0 = ((ch) & 3) * 64; \
        const char* _gA = (const char*)(a_srcs[_term] + (size_t)mt * 128 * N_ + _kk0); \
        const char* _gB = (const char*)(b_srcs[_term] + (size_t)j0 * N_ + _kk0); \
        uint32_t _sa = s_base + ((ch) & 1) * 2u * TILE_BYTES; \
        uint32_t _sb = _sa + TILE_BYTES; \
        _Pragma("unroll") \
        for (int _it = 0; _it < 4; ++_it) { \
            CP_ASYNC16(_sa + (uint32_t)st_sw[_it] * 16u, _gA + (size_t)st_r[_it] * 16); \
            CP_ASYNC16(_sb + (uint32_t)st_sw[_it] * 16u, _gB + (size_t)st_r[_it] * 16); \
        } \
        CP_COMMIT(); \
    } while (0)

    int a_r15 = lane & 15;
    int a_kh  = lane >> 4;
    int b_row = ((lane & 16) >> 1) + (lane & 7);
    int b_kh  = (lane >> 3) & 1;

    float acc[4][4][4];
#pragma unroll
    for (int i = 0; i < 4; ++i)
#pragma unroll
        for (int j = 0; j < 4; ++j)
#pragma unroll
            for (int q = 0; q < 4; ++q) acc[i][j][q] = 0.f;

    ISSUE_CHUNK(0);

    for (int ch = 0; ch < 12; ++ch) {
        if (ch + 1 < 12) {
            ISSUE_CHUNK(ch + 1);
            CP_WAIT1();
        } else {
            CP_WAIT0();
        }
        __syncthreads();

        uint32_t as_base = s_base + (ch & 1) * 2u * TILE_BYTES;
        uint32_t bs_base = as_base + TILE_BYTES;

#pragma unroll
        for (int ks = 0; ks < 4; ++ks) {
            uint32_t afr[4][4];
            uint32_t bfr[4][2];
#pragma unroll
            for (int tm = 0; tm < 4; ++tm) {
                int row = wm * 64 + tm * 16 + a_r15;
                int c = (2 * ks + a_kh) ^ (a_r15 & 7);
                uint32_t addr = as_base + (uint32_t)(row * 64 + c * 8) * 2u;
                LDM_X4(afr[tm][0], afr[tm][1], afr[tm][2], afr[tm][3], addr);
            }
#pragma unroll
            for (int tn2 = 0; tn2 < 2; ++tn2) {
                int row = wn * 32 + tn2 * 16 + b_row;
                int c = (2 * ks + b_kh) ^ (b_row & 7);
                uint32_t addr = bs_base + (uint32_t)(row * 64 + c * 8) * 2u;
                uint32_t r0, r1, r2, r3;
                LDM_X4(r0, r1, r2, r3, addr);
                bfr[tn2 * 2 + 0][0] = r0; bfr[tn2 * 2 + 0][1] = r1;
                bfr[tn2 * 2 + 1][0] = r2; bfr[tn2 * 2 + 1][1] = r3;
            }
#pragma unroll
            for (int tm = 0; tm < 4; ++tm)
#pragma unroll
                for (int tn = 0; tn < 4; ++tn)
                    MMA16816(acc[tm][tn], afr[tm], bfr[tn]);
        }
        __syncthreads();
    }

    int qr = lane >> 2;
    int qc = (lane & 3) * 2;
#pragma unroll
    for (int tm = 0; tm < 4; ++tm) {
#pragma unroll
        for (int tn = 0; tn < 4; ++tn) {
            int colt = wn * 32 + tn * 8 + qc;
            size_t m0 = (size_t)mt * 128 + wm * 64 + tm * 16 + qr;
            float bx = bias_s[colt], by = bias_s[colt + 1];
            float2 v0 = make_float2(acc[tm][tn][0] + bx, acc[tm][tn][1] + by);
            float2 v1 = make_float2(acc[tm][tn][2] + bx, acc[tm][tn][3] + by);
            *(float2*)(g_G1 + m0 * G_ + j0 + colt) = v0;
            *(float2*)(g_G1 + (m0 + 8) * G_ + j0 + colt) = v1;
        }
    }
}

// ---------------- K4: persistent recurrence ----------------
// Tree barrier with GLOBAL semantics (proven R7): 8 leaves x 16 -> root x 8 -> gen.
__device__ __forceinline__ void grid_sync_tree(int leaf) {
    __threadfence();
    __syncthreads();
    if (threadIdx.x == 0) {
        unsigned gen = g_gen;
        if (atomicAdd(&g_cnt_leaf[leaf], 1u) == 15u) {
            g_cnt_leaf[leaf] = 0;
            if (atomicAdd(&g_cnt_root, 1u) == 7u) {
                g_cnt_root = 0;
                __threadfence();
                g_gen = gen + 1u;
            }
        }
        while (g_gen == gen) { __nanosleep(64); }
        __threadfence();
    }
    __syncthreads();
}

// grid (8, 16): blockIdx.x -> 32-batch tile, blockIdx.y -> 16-hidden tile.
// 128 threads = 4 warps; warp = (bgp, hidp); lane = ks*8 + hid3.
// Thread: 16 batches x 4 gates over a 64-k slice (k = ks*64 + kk).
// FMA2 pairs over BATCHES (natural h pairs); W pre-duplicated in SMEM (static).
// SMEM: Ws [k256][half2][hid16][q01] dup u64 = 128KB; Hs [k256][b32] fp32 = 32KB.
// Warp-internal k-split reduced via shfl_xor(8/16) + add.f32x2.
__global__ void __launch_bounds__(128, 1) k_recur(
        const float* __restrict__ Whh, float* __restrict__ out_enc) {
    extern __shared__ float sm[];
    unsigned long long* Wsu = (unsigned long long*)sm;   // 16384 u64 (128 KB)
    float* Hsf = sm + 32768;                             // 8192 floats (32 KB)
    const ulonglong2* Ws2 = (const ulonglong2*)sm;
    const ulonglong2* Hs2 = (const ulonglong2*)Hsf;
    float4* Hs4 = (float4*)Hsf;

    int tid = threadIdx.x;            // 128
    int b0  = blockIdx.x * 32;
    int h0  = blockIdx.y * 16;
    int leaf = blockIdx.x;

    // Build duplicated W tile once: u64 idx = k*64 + half*32 + hid*2 + qlo,
    // value = (w,w) with w = Whh[(q*H + h0+hid)*N + k], q = half*2 + qlo.
    for (int idx = tid; idx < 16384; idx += 128) {
        int k = idx >> 6;
        int r = idx & 63;
        int half = r >> 5;
        int hh = (r >> 1) & 15;
        int qlo = r & 1;
        int q = half * 2 + qlo;
        float w = Whh[(size_t)(q * H_ + h0 + hh) * N_ + k];
        Wsu[idx] = pk2(w, w);
    }

    int lane = tid & 31;
    int ks   = lane >> 3;             // 0..3  k-slice
    int bgp  = (tid >> 5) & 1;        // 0..1  batch half (16 batches)
    int hidp = tid >> 6;              // 0..1
    int hid  = hidp * 8 + (lane & 7); // 0..15

    float creg[4] = {0.f, 0.f, 0.f, 0.f};
    __syncthreads();

    // prefetch G1 for t=0: 4 owned batches x 4 gates
    float g1v[4][4];
#pragma unroll
    for (int i = 0; i < 4; ++i) {
        int b = b0 + bgp * 16 + ks * 4 + i;
        const float* g1 = g_G1 + ((size_t)b) * G_ + h0 + hid;
        g1v[i][0] = __ldcg(g1 + 0);
        g1v[i][1] = __ldcg(g1 + 256);
        g1v[i][2] = __ldcg(g1 + 512);
        g1v[i][3] = __ldcg(g1 + 768);
    }

    for (int t = 0; t < T_; ++t) {
        // stage h slice [256 k][32 b] NATURAL layout (no duplication)
        const float4* gh4 = (const float4*)g_hbuf[t & 1];
#pragma unroll
        for (int it = 0; it < 16; ++it) {
            int idx = tid + it * 128;         // 0..2047
            int k = idx >> 3;
            int j = idx & 7;
            Hs4[k * 8 + j] = __ldcg(gh4 + k * 64 + (b0 >> 2) + j);
        }
        __syncthreads();

        // partial gates over this thread's 64-k slice
        unsigned long long acc[4][8];
#pragma unroll
        for (int q = 0; q < 4; ++q)
#pragma unroll
            for (int bp = 0; bp < 8; ++bp) acc[q][bp] = 0ull;

        const ulonglong2* wp = Ws2 + (size_t)(ks * 64) * 32 + hid;
        const ulonglong2* hp = Hs2 + (size_t)(ks * 64) * 8 + bgp * 4;
#pragma unroll 4
        for (int kk = 0; kk < 64; ++kk) {
            ulonglong2 w01 = wp[0];           // (wi,wi),(wf,wf)
            ulonglong2 w23 = wp[16];          // (wg,wg),(wo,wo)
            ulonglong2 hA = hp[0];            // (h0,h1),(h2,h3)
            ulonglong2 hB = hp[1];            // (h4,h5),(h6,h7)
            ulonglong2 hC = hp[2];
            ulonglong2 hD = hp[3];
#define ROWQ(q, wv) \
            FMA2(acc[q][0], hA.x, wv); FMA2(acc[q][1], hA.y, wv); \
            FMA2(acc[q][2], hB.x, wv); FMA2(acc[q][3], hB.y, wv); \
            FMA2(acc[q][4], hC.x, wv); FMA2(acc[q][5], hC.y, wv); \
            FMA2(acc[q][6], hD.x, wv); FMA2(acc[q][7], hD.y, wv);
            ROWQ(0, w01.x) ROWQ(1, w01.y) ROWQ(2, w23.x) ROWQ(3, w23.y)
#undef ROWQ
            wp += 32;
            hp += 8;
        }

        // warp-internal k-split reduction (ks bits = lane bits 3,4)
#pragma unroll
        for (int q = 0; q < 4; ++q)
#pragma unroll
            for (int bp = 0; bp < 8; ++bp) {
                unsigned long long v = acc[q][bp];
                v = addf2(v, __shfl_xor_sync(0xffffffffu, v, 8));
                v = addf2(v, __shfl_xor_sync(0xffffffffu, v, 16));
                acc[q][bp] = v;
            }

        // extract this ks-lane's 4 owned batches
        float ga[4][4];   // [i][q]
#pragma unroll
        for (int q = 0; q < 4; ++q) {
            upk2(acc[q][ks * 2],     ga[0][q], ga[1][q]);
            upk2(acc[q][ks * 2 + 1], ga[2][q], ga[3][q]);
        }

        // fused LSTM cell update + output store
        float* ghw = g_hbuf[(t + 1) & 1];
#pragma unroll
        for (int i = 0; i < 4; ++i) {
            int b = b0 + bgp * 16 + ks * 4 + i;
            float ig = sigf(ga[i][0] + g1v[i][0]);
            float fg = sigf(ga[i][1] + g1v[i][1]);
            float g_ = tanhfast(ga[i][2] + g1v[i][2]);
            float og = sigf(ga[i][3] + g1v[i][3]);
            float c = fmaf(fg, creg[i], ig * g_);
            creg[i] = c;
            float hn = og * tanhfast(c);
            __stcg(&ghw[(h0 + hid) * B_ + b], hn);
            out_enc[((size_t)b * T_ + t) * H_ + h0 + hid] = hn;
        }

        if (t + 1 < T_) {
            // prefetch G1 for t+1 BEFORE the barrier (hides DRAM latency)
#pragma unroll
            for (int i = 0; i < 4; ++i) {
                int b = b0 + bgp * 16 + ks * 4 + i;
                const float* g1 = g_G1 + ((size_t)(t + 1) * B_ + b) * G_ + h0 + hid;
                g1v[i][0] = __ldcg(g1 + 0);
                g1v[i][1] = __ldcg(g1 + 256);
                g1v[i][2] = __ldcg(g1 + 512);
                g1v[i][3] = __ldcg(g1 + 768);
            }
            grid_sync_tree(leaf);
        }
    }
}

// ---------------- launch ----------------
extern "C" void kernel_launch(void* const* d_in, const int* in_sizes, int n_in,
                              void* d_out, int out_size) {
    const float* input  = (const float*)d_in[0];
    const float* W_ih   = (const float*)d_in[1];
    const float* W_hh   = (const float*)d_in[2];
    const float* b_ih   = (const float*)d_in[3];
    const float* b_hh   = (const float*)d_in[4];
    const float* attn_w = (const float*)d_in[5];
    float* out = (float*)d_out;

    cudaFuncSetAttribute(k_recur, cudaFuncAttributeMaxDynamicSharedMemorySize, 163840);

    // K1: attention weights (+ zero h state)
    k_attn<<<B_, N_>>>(input, attn_w);
    // K2: weighted input -> output region 0 + bf16 hi/lo staging
    k_weighted<<<B_ * T_, N_>>>(input, out);
    // K2b: W_ih bf16 hi/lo
    k_convB<<<G_, N_>>>(W_ih);
    // K3: HMMA split-bf16 GEMM into g_G1, cp.async double-buffered
    dim3 g3(8, 1024);
    k_gemm_mma<<<g3, 256>>>(b_ih, b_hh);
    // K4: persistent recurrence -> output region 1 (k-split FMA2, tree barrier)
    dim3 g4(8, 16);
    k_recur<<<g4, 128, 163840>>>(W_hh, out + ENC_OFF);
}

// round 11
// speedup vs baseline: 1.5949x; 1.1296x over previous
#include <cuda_runtime.h>
#include <cuda_bf16.h>
#include <cstdint>

// Problem constants
#define B_ 256
#define T_ 512          // TM1
#define N_ 256
#define H_ 256
#define G_ 1024         // 4*H
#define ENC_OFF ((size_t)B_ * T_ * N_)   // offset of input_encoded in d_out

// ---------------- device scratch (no cudaMalloc allowed) ----------------
__device__ float g_attn[B_ * N_];                      // softmax(x_scores)
__device__ float g_G1[(size_t)T_ * B_ * G_];           // gates pre-recurrence, [m=t*B+b][j]
__device__ float g_hbuf[2][H_ * B_];                   // ping-pong hidden state, [h][b]
__device__ __nv_bfloat16 g_Ahi[(size_t)T_ * B_ * N_];  // weighted, bf16 hi
__device__ __nv_bfloat16 g_Alo[(size_t)T_ * B_ * N_];  // weighted, bf16 lo
__device__ __nv_bfloat16 g_Bhi[G_ * N_];               // W_ih, bf16 hi
__device__ __nv_bfloat16 g_Blo[G_ * N_];               // W_ih, bf16 lo
// Group barrier: MONOTONIC counters (never reset -> no lost-arrival race),
// 128B padded per group, zeroed by k_attn at the start of every launch.
__device__ unsigned g_cnt_grp[256];

// ---------------- packed fp32x2 helpers ----------------
#define FMA2(d, a, b) asm("fma.rn.f32x2 %0, %1, %2, %0;" : "+l"(d) : "l"(a), "l"(b))

__device__ __forceinline__ unsigned long long pk2(float lo, float hi) {
    unsigned long long r;
    asm("mov.b64 %0, {%1, %2};" : "=l"(r) : "f"(lo), "f"(hi));
    return r;
}
__device__ __forceinline__ void upk2(unsigned long long v, float& lo, float& hi) {
    asm("mov.b64 {%0, %1}, %2;" : "=f"(lo), "=f"(hi) : "l"(v));
}
__device__ __forceinline__ unsigned long long addf2(unsigned long long a, unsigned long long b) {
    unsigned long long r;
    asm("add.rn.f32x2 %0, %1, %2;" : "=l"(r) : "l"(a), "l"(b));
    return r;
}
__device__ __forceinline__ float sigf(float x) {
    return __fdividef(1.f, 1.f + __expf(-x));
}
__device__ __forceinline__ float tanhfast(float x) {
    return __fdividef(2.f, 1.f + __expf(-2.f * x)) - 1.f;
}
__device__ __forceinline__ uint32_t smem_to_u32(const void* p) {
    uint32_t a;
    asm("{ .reg .u64 t; cvta.to.shared.u64 t, %1; cvt.u32.u64 %0, t; }" : "=r"(a) : "l"(p));
    return a;
}

// ---------------- cp.async helpers ----------------
#define CP_ASYNC16(dst, src) \
    asm volatile("cp.async.cg.shared.global [%0], [%1], 16;" :: "r"(dst), "l"(src) : "memory")
#define CP_COMMIT() asm volatile("cp.async.commit_group;" ::: "memory")
#define CP_WAIT1() asm volatile("cp.async.wait_group 1;" ::: "memory")
#define CP_WAIT0() asm volatile("cp.async.wait_group 0;" ::: "memory")

// ---------------- K1: x_scores + softmax -> attn, zero h buffer + counters ----
__global__ void k_attn(const float* __restrict__ in, const float* __restrict__ attn_w) {
    __shared__ float wx[T_];
    __shared__ float red[N_];
    int b = blockIdx.x;
    int n = threadIdx.x;

    if (b == 0) g_cnt_grp[n] = 0;    // reset group-barrier counters every launch

    wx[n]       = attn_w[2 * H_ + n];
    wx[n + 256] = attn_w[2 * H_ + 256 + n];
    __syncthreads();

    const float* p = in + (size_t)b * T_ * N_ + n;
    float acc = 0.f;
#pragma unroll 8
    for (int t = 0; t < T_; ++t)
        acc = fmaf(p[(size_t)t * N_], wx[t], acc);

    red[n] = acc;
    __syncthreads();
    for (int s = 128; s > 0; s >>= 1) {
        if (n < s) red[n] = fmaxf(red[n], red[n + s]);
        __syncthreads();
    }
    float mx = red[0];
    __syncthreads();
    float e = expf(acc - mx);
    red[n] = e;
    __syncthreads();
    for (int s = 128; s > 0; s >>= 1) {
        if (n < s) red[n] += red[n + s];
        __syncthreads();
    }
    g_attn[b * N_ + n] = e / red[0];
    g_hbuf[0][b * N_ + n] = 0.f;
}

// ---------------- K2: weighted = attn * x -> out region 0 + bf16 hi/lo ---------
__global__ void k_weighted(const float* __restrict__ in, float* __restrict__ out) {
    int blk = blockIdx.x;            // b*T_ + t
    int b = blk >> 9;
    int t = blk & 511;
    int n = threadIdx.x;
    size_t idx = (size_t)blk * N_ + n;
    float w = g_attn[b * N_ + n] * in[idx];
    out[idx] = w;
    size_t m = (size_t)t * B_ + b;   // GEMM row index
    __nv_bfloat16 hi = __float2bfloat16(w);
    __nv_bfloat16 lo = __float2bfloat16(w - __bfloat162float(hi));
    g_Ahi[m * N_ + n] = hi;
    g_Alo[m * N_ + n] = lo;
}

// ---------------- K2b: W_ih -> bf16 hi/lo ----------------
__global__ void k_convB(const float* __restrict__ Wih) {
    int j = blockIdx.x;
    int k = threadIdx.x;
    float v = Wih[(size_t)j * N_ + k];
    __nv_bfloat16 hi = __float2bfloat16(v);
    __nv_bfloat16 lo = __float2bfloat16(v - __bfloat162float(hi));
    g_Bhi[j * N_ + k] = hi;
    g_Blo[j * N_ + k] = lo;
}

// ---------------- K3: mma.sync bf16 split GEMM, cp.async double-buffered -------
// (unchanged — proven at 517us)
#define LDM_X4(r0, r1, r2, r3, a) \
    asm volatile("ldmatrix.sync.aligned.m8n8.x4.shared.b16 {%0,%1,%2,%3}, [%4];" \
                 : "=r"(r0), "=r"(r1), "=r"(r2), "=r"(r3) : "r"(a))
#define MMA16816(c, a, b) \
    asm volatile("mma.sync.aligned.m16n8k16.row.col.f32.bf16.bf16.f32 " \
                 "{%0,%1,%2,%3}, {%4,%5,%6,%7}, {%8,%9}, {%0,%1,%2,%3};" \
                 : "+f"((c)[0]), "+f"((c)[1]), "+f"((c)[2]), "+f"((c)[3]) \
                 : "r"((a)[0]), "r"((a)[1]), "r"((a)[2]), "r"((a)[3]), "r"((b)[0]), "r"((b)[1]))

#define TILE_BYTES 16384           // 128 x 64 bf16

__global__ void __launch_bounds__(256) k_gemm_mma(
        const float* __restrict__ b_ih, const float* __restrict__ b_hh) {
    __shared__ __align__(16) __nv_bfloat16 Sb[4 * 128 * 64];   // 64 KB
    __shared__ float bias_s[128];

    int tid = threadIdx.x;
    int wid = tid >> 5;
    int lane = tid & 31;
    int nt = blockIdx.x;             // 0..7  gate tile
    int mt = blockIdx.y;             // 0..1023 m tile
    int j0 = nt * 128;
    int wm = wid >> 2;               // 0..1
    int wn = wid & 3;                // 0..3

    if (tid < 128) bias_s[tid] = b_ih[j0 + tid] + b_hh[j0 + tid];

    uint32_t s_base = smem_to_u32(Sb);

    int st_r[4], st_sw[4];
#pragma unroll
    for (int it = 0; it < 4; ++it) {
        int idx = tid + it * 256;        // 0..1023
        int r = idx >> 3;
        int kg = idx & 7;
        st_r[it] = r * 32 + kg;
        st_sw[it] = r * 8 + (kg ^ (r & 7));
    }

    const __nv_bfloat16* a_srcs[3] = {g_Ahi, g_Alo, g_Ahi};
    const __nv_bfloat16* b_srcs[3] = {g_Bhi, g_Bhi, g_Blo};

#define ISSUE_CHUNK(ch) do { \
        int _term = (ch) >> 2; \
        int _kk0 = ((ch) & 3) * 64; \
        const char* _gA = (const char*)(a_srcs[_term] + (size_t)mt * 128 * N_ + _kk0); \
        const char* _gB = (const char*)(b_srcs[_term] + (size_t)j0 * N_ + _kk0); \
        uint32_t _sa = s_base + ((ch) & 1) * 2u * TILE_BYTES; \
        uint32_t _sb = _sa + TILE_BYTES; \
        _Pragma("unroll") \
        for (int _it = 0; _it < 4; ++_it) { \
            CP_ASYNC16(_sa + (uint32_t)st_sw[_it] * 16u, _gA + (size_t)st_r[_it] * 16); \
            CP_ASYNC16(_sb + (uint32_t)st_sw[_it] * 16u, _gB + (size_t)st_r[_it] * 16); \
        } \
        CP_COMMIT(); \
    } while (0)

    int a_r15 = lane & 15;
    int a_kh  = lane >> 4;
    int b_row = ((lane & 16) >> 1) + (lane & 7);
    int b_kh  = (lane >> 3) & 1;

    float acc[4][4][4];
#pragma unroll
    for (int i = 0; i < 4; ++i)
#pragma unroll
        for (int j = 0; j < 4; ++j)
#pragma unroll
            for (int q = 0; q < 4; ++q) acc[i][j][q] = 0.f;

    ISSUE_CHUNK(0);

    for (int ch = 0; ch < 12; ++ch) {
        if (ch + 1 < 12) {
            ISSUE_CHUNK(ch + 1);
            CP_WAIT1();
        } else {
            CP_WAIT0();
        }
        __syncthreads();

        uint32_t as_base = s_base + (ch & 1) * 2u * TILE_BYTES;
        uint32_t bs_base = as_base + TILE_BYTES;

#pragma unroll
        for (int ks = 0; ks < 4; ++ks) {
            uint32_t afr[4][4];
            uint32_t bfr[4][2];
#pragma unroll
            for (int tm = 0; tm < 4; ++tm) {
                int row = wm * 64 + tm * 16 + a_r15;
                int c = (2 * ks + a_kh) ^ (a_r15 & 7);
                uint32_t addr = as_base + (uint32_t)(row * 64 + c * 8) * 2u;
                LDM_X4(afr[tm][0], afr[tm][1], afr[tm][2], afr[tm][3], addr);
            }
#pragma unroll
            for (int tn2 = 0; tn2 < 2; ++tn2) {
                int row = wn * 32 + tn2 * 16 + b_row;
                int c = (2 * ks + b_kh) ^ (b_row & 7);
                uint32_t addr = bs_base + (uint32_t)(row * 64 + c * 8) * 2u;
                uint32_t r0, r1, r2, r3;
                LDM_X4(r0, r1, r2, r3, addr);
                bfr[tn2 * 2 + 0][0] = r0; bfr[tn2 * 2 + 0][1] = r1;
                bfr[tn2 * 2 + 1][0] = r2; bfr[tn2 * 2 + 1][1] = r3;
            }
#pragma unroll
            for (int tm = 0; tm < 4; ++tm)
#pragma unroll
                for (int tn = 0; tn < 4; ++tn)
                    MMA16816(acc[tm][tn], afr[tm], bfr[tn]);
        }
        __syncthreads();
    }

    int qr = lane >> 2;
    int qc = (lane & 3) * 2;
#pragma unroll
    for (int tm = 0; tm < 4; ++tm) {
#pragma unroll
        for (int tn = 0; tn < 4; ++tn) {
            int colt = wn * 32 + tn * 8 + qc;
            size_t m0 = (size_t)mt * 128 + wm * 64 + tm * 16 + qr;
            float bx = bias_s[colt], by = bias_s[colt + 1];
            float2 v0 = make_float2(acc[tm][tn][0] + bx, acc[tm][tn][1] + by);
            float2 v1 = make_float2(acc[tm][tn][2] + bx, acc[tm][tn][3] + by);
            *(float2*)(g_G1 + m0 * G_ + j0 + colt) = v0;
            *(float2*)(g_G1 + (m0 + 8) * G_ + j0 + colt) = v1;
        }
    }
}

// ---------------- K4: persistent recurrence ----------------
// Group barrier: only the 16 CTAs sharing a batch tile (blockIdx.x) sync.
// MONOTONIC counter per group (zeroed by k_attn each launch): arrival =
// atomicAdd; wait = spin until cnt >= 16*(t+1). No reset -> no race.
// grid (8, 16): blockIdx.x -> 32-batch tile (= group), blockIdx.y -> 16-hid tile.
// 128 threads = 4 warps; thread: 16 batches x 4 gates over a 64-k slice.
// SMEM: Ws [k256][half2][hid16][q01] dup u64 = 128KB; Hs [k256][b32] fp32 = 32KB.
__global__ void __launch_bounds__(128, 1) k_recur(
        const float* __restrict__ Whh, float* __restrict__ out_enc) {
    extern __shared__ float sm[];
    unsigned long long* Wsu = (unsigned long long*)sm;   // 16384 u64 (128 KB)
    float* Hsf = sm + 32768;                             // 8192 floats (32 KB)
    const ulonglong2* Ws2 = (const ulonglong2*)sm;
    const ulonglong2* Hs2 = (const ulonglong2*)Hsf;
    float4* Hs4 = (float4*)Hsf;

    int tid = threadIdx.x;            // 128
    int b0  = blockIdx.x * 32;
    int h0  = blockIdx.y * 16;
    int grp = blockIdx.x;             // 8 groups x 16 CTAs

    // Build duplicated W tile once: u64 idx = k*64 + half*32 + hid*2 + qlo,
    // value = (w,w) with w = Whh[(q*H + h0+hid)*N + k], q = half*2 + qlo.
    for (int idx = tid; idx < 16384; idx += 128) {
        int k = idx >> 6;
        int r = idx & 63;
        int half = r >> 5;
        int hh = (r >> 1) & 15;
        int qlo = r & 1;
        int q = half * 2 + qlo;
        float w = Whh[(size_t)(q * H_ + h0 + hh) * N_ + k];
        Wsu[idx] = pk2(w, w);
    }

    int lane = tid & 31;
    int ks   = lane >> 3;             // 0..3  k-slice
    int bgp  = (tid >> 5) & 1;        // 0..1  batch half (16 batches)
    int hidp = tid >> 6;              // 0..1
    int hid  = hidp * 8 + (lane & 7); // 0..15

    float creg[4] = {0.f, 0.f, 0.f, 0.f};
    __syncthreads();

    // prefetch G1 for t=0: 4 owned batches x 4 gates
    float g1v[4][4];
#pragma unroll
    for (int i = 0; i < 4; ++i) {
        int b = b0 + bgp * 16 + ks * 4 + i;
        const float* g1 = g_G1 + ((size_t)b) * G_ + h0 + hid;
        g1v[i][0] = __ldcg(g1 + 0);
        g1v[i][1] = __ldcg(g1 + 256);
        g1v[i][2] = __ldcg(g1 + 512);
        g1v[i][3] = __ldcg(g1 + 768);
    }

    for (int t = 0; t < T_; ++t) {
        // stage h slice [256 k][32 b] NATURAL layout
        const float4* gh4 = (const float4*)g_hbuf[t & 1];
#pragma unroll
        for (int it = 0; it < 16; ++it) {
            int idx = tid + it * 128;         // 0..2047
            int k = idx >> 3;
            int j = idx & 7;
            Hs4[k * 8 + j] = __ldcg(gh4 + k * 64 + (b0 >> 2) + j);
        }
        __syncthreads();

        // partial gates over this thread's 64-k slice
        unsigned long long acc[4][8];
#pragma unroll
        for (int q = 0; q < 4; ++q)
#pragma unroll
            for (int bp = 0; bp < 8; ++bp) acc[q][bp] = 0ull;

        const ulonglong2* wp = Ws2 + (size_t)(ks * 64) * 32 + hid;
        const ulonglong2* hp = Hs2 + (size_t)(ks * 64) * 8 + bgp * 4;
#pragma unroll 4
        for (int kk = 0; kk < 64; ++kk) {
            ulonglong2 w01 = wp[0];           // (wi,wi),(wf,wf)
            ulonglong2 w23 = wp[16];          // (wg,wg),(wo,wo)
            ulonglong2 hA = hp[0];            // (h0,h1),(h2,h3)
            ulonglong2 hB = hp[1];            // (h4,h5),(h6,h7)
            ulonglong2 hC = hp[2];
            ulonglong2 hD = hp[3];
#define ROWQ(q, wv) \
            FMA2(acc[q][0], hA.x, wv); FMA2(acc[q][1], hA.y, wv); \
            FMA2(acc[q][2], hB.x, wv); FMA2(acc[q][3], hB.y, wv); \
            FMA2(acc[q][4], hC.x, wv); FMA2(acc[q][5], hC.y, wv); \
            FMA2(acc[q][6], hD.x, wv); FMA2(acc[q][7], hD.y, wv);
            ROWQ(0, w01.x) ROWQ(1, w01.y) ROWQ(2, w23.x) ROWQ(3, w23.y)
#undef ROWQ
            wp += 32;
            hp += 8;
        }

        // warp-internal k-split reduction (ks bits = lane bits 3,4)
#pragma unroll
        for (int q = 0; q < 4; ++q)
#pragma unroll
            for (int bp = 0; bp < 8; ++bp) {
                unsigned long long v = acc[q][bp];
                v = addf2(v, __shfl_xor_sync(0xffffffffu, v, 8));
                v = addf2(v, __shfl_xor_sync(0xffffffffu, v, 16));
                acc[q][bp] = v;
            }

        // extract this ks-lane's 4 owned batches
        float ga[4][4];   // [i][q]
#pragma unroll
        for (int q = 0; q < 4; ++q) {
            upk2(acc[q][ks * 2],     ga[0][q], ga[1][q]);
            upk2(acc[q][ks * 2 + 1], ga[2][q], ga[3][q]);
        }

        // fused LSTM cell update + output store
        float* ghw = g_hbuf[(t + 1) & 1];
#pragma unroll
        for (int i = 0; i < 4; ++i) {
            int b = b0 + bgp * 16 + ks * 4 + i;
            float ig = sigf(ga[i][0] + g1v[i][0]);
            float fg = sigf(ga[i][1] + g1v[i][1]);
            float g_ = tanhfast(ga[i][2] + g1v[i][2]);
            float og = sigf(ga[i][3] + g1v[i][3]);
            float c = fmaf(fg, creg[i], ig * g_);
            creg[i] = c;
            float hn = og * tanhfast(c);
            __stcg(&ghw[(h0 + hid) * B_ + b], hn);
            out_enc[((size_t)b * T_ + t) * H_ + h0 + hid] = hn;
        }

        if (t + 1 < T_) {
            // prefetch G1 for t+1 (loads fly during barrier)
#pragma unroll
            for (int i = 0; i < 4; ++i) {
                int b = b0 + bgp * 16 + ks * 4 + i;
                const float* g1 = g_G1 + ((size_t)(t + 1) * B_ + b) * G_ + h0 + hid;
                g1v[i][0] = __ldcg(g1 + 0);
                g1v[i][1] = __ldcg(g1 + 256);
                g1v[i][2] = __ldcg(g1 + 512);
                g1v[i][3] = __ldcg(g1 + 768);
            }
            // ---- group barrier (16 CTAs, monotonic counter) ----
            __threadfence();              // h stores visible before arrival
            __syncthreads();              // also guards Hs reuse next step
            if (tid == 0) atomicAdd(&g_cnt_grp[grp * 32], 1u);
            unsigned target = (unsigned)(t + 1) * 16u;
            volatile unsigned* cp = &g_cnt_grp[grp * 32];
            while (*cp < target) { __nanosleep(32); }
            __threadfence();              // acquire peers' h stores
        }
    }
}

// ---------------- launch ----------------
extern "C" void kernel_launch(void* const* d_in, const int* in_sizes, int n_in,
                              void* d_out, int out_size) {
    const float* input  = (const float*)d_in[0];
    const float* W_ih   = (const float*)d_in[1];
    const float* W_hh   = (const float*)d_in[2];
    const float* b_ih   = (const float*)d_in[3];
    const float* b_hh   = (const float*)d_in[4];
    const float* attn_w = (const float*)d_in[5];
    float* out = (float*)d_out;

    cudaFuncSetAttribute(k_recur, cudaFuncAttributeMaxDynamicSharedMemorySize, 163840);

    // K1: attention weights (+ zero h state, zero group counters)
    k_attn<<<B_, N_>>>(input, attn_w);
    // K2: weighted input -> output region 0 + bf16 hi/lo staging
    k_weighted<<<B_ * T_, N_>>>(input, out);
    // K2b: W_ih bf16 hi/lo
    k_convB<<<G_, N_>>>(W_ih);
    // K3: HMMA split-bf16 GEMM into g_G1, cp.async double-buffered
    dim3 g3(8, 1024);
    k_gemm_mma<<<g3, 256>>>(b_ih, b_hh);
    // K4: persistent recurrence -> output region 1 (16-CTA group barrier)
    dim3 g4(8, 16);
    k_recur<<<g4, 128, 163840>>>(W_hh, out + ENC_OFF);
}

// round 12
// speedup vs baseline: 2.2878x; 1.4345x over previous
#include <cuda_runtime.h>
#include <cuda_bf16.h>
#include <cstdint>

// Problem constants
#define B_ 256
#define T_ 512          // TM1
#define N_ 256
#define H_ 256
#define G_ 1024         // 4*H
#define ENC_OFF ((size_t)B_ * T_ * N_)   // offset of input_encoded in d_out

// ---------------- device scratch (no cudaMalloc allowed) ----------------
__device__ float g_attn[B_ * N_];                      // softmax(x_scores)
__device__ float g_G1[(size_t)T_ * B_ * G_];           // gates pre-recurrence, [m=t*B+b][j]
__device__ float g_hbuf[2][B_ * H_];                   // ping-pong hidden state, [b][h]
__device__ __nv_bfloat16 g_Ahi[(size_t)T_ * B_ * N_];  // weighted, bf16 hi
__device__ __nv_bfloat16 g_Alo[(size_t)T_ * B_ * N_];  // weighted, bf16 lo
__device__ __nv_bfloat16 g_Bhi[G_ * N_];               // W_ih, bf16 hi
__device__ __nv_bfloat16 g_Blo[G_ * N_];               // W_ih, bf16 lo
// Group barrier: MONOTONIC counters (never reset -> no lost-arrival race),
// 128B padded per group, zeroed by k_attn at the start of every launch.
__device__ unsigned g_cnt_grp[256];

// ---------------- helpers ----------------
__device__ __forceinline__ float sigf(float x) {
    return __fdividef(1.f, 1.f + __expf(-x));
}
__device__ __forceinline__ float tanhfast(float x) {
    return __fdividef(2.f, 1.f + __expf(-2.f * x)) - 1.f;
}
__device__ __forceinline__ uint32_t smem_to_u32(const void* p) {
    uint32_t a;
    asm("{ .reg .u64 t; cvta.to.shared.u64 t, %1; cvt.u32.u64 %0, t; }" : "=r"(a) : "l"(p));
    return a;
}
__device__ __forceinline__ void split4(float4 v, uint2& hi, uint2& lo) {
    __nv_bfloat16 hx = __float2bfloat16(v.x);
    __nv_bfloat16 hy = __float2bfloat16(v.y);
    __nv_bfloat16 hz = __float2bfloat16(v.z);
    __nv_bfloat16 hw = __float2bfloat16(v.w);
    __nv_bfloat16 lx = __float2bfloat16(v.x - __bfloat162float(hx));
    __nv_bfloat16 ly = __float2bfloat16(v.y - __bfloat162float(hy));
    __nv_bfloat16 lz = __float2bfloat16(v.z - __bfloat162float(hz));
    __nv_bfloat16 lw = __float2bfloat16(v.w - __bfloat162float(hw));
    __nv_bfloat162 h01(hx, hy), h23(hz, hw), l01(lx, ly), l23(lz, lw);
    hi.x = *reinterpret_cast<uint32_t*>(&h01);
    hi.y = *reinterpret_cast<uint32_t*>(&h23);
    lo.x = *reinterpret_cast<uint32_t*>(&l01);
    lo.y = *reinterpret_cast<uint32_t*>(&l23);
}

// ---------------- cp.async helpers ----------------
#define CP_ASYNC16(dst, src) \
    asm volatile("cp.async.cg.shared.global [%0], [%1], 16;" :: "r"(dst), "l"(src) : "memory")
#define CP_COMMIT() asm volatile("cp.async.commit_group;" ::: "memory")
#define CP_WAIT1() asm volatile("cp.async.wait_group 1;" ::: "memory")
#define CP_WAIT0() asm volatile("cp.async.wait_group 0;" ::: "memory")

// ---------------- mma helpers (proven in K3) ----------------
#define LDM_X4(r0, r1, r2, r3, a) \
    asm volatile("ldmatrix.sync.aligned.m8n8.x4.shared.b16 {%0,%1,%2,%3}, [%4];" \
                 : "=r"(r0), "=r"(r1), "=r"(r2), "=r"(r3) : "r"(a))
#define MMA16816(c, a, b) \
    asm volatile("mma.sync.aligned.m16n8k16.row.col.f32.bf16.bf16.f32 " \
                 "{%0,%1,%2,%3}, {%4,%5,%6,%7}, {%8,%9}, {%0,%1,%2,%3};" \
                 : "+f"((c)[0]), "+f"((c)[1]), "+f"((c)[2]), "+f"((c)[3]) \
                 : "r"((a)[0]), "r"((a)[1]), "r"((a)[2]), "r"((a)[3]), "r"((b)[0]), "r"((b)[1]))

// ---------------- K1: x_scores + softmax -> attn, zero h buffer + counters ----
__global__ void k_attn(const float* __restrict__ in, const float* __restrict__ attn_w) {
    __shared__ float wx[T_];
    __shared__ float red[N_];
    int b = blockIdx.x;
    int n = threadIdx.x;

    if (b == 0) g_cnt_grp[n] = 0;    // reset group-barrier counters every launch

    wx[n]       = attn_w[2 * H_ + n];
    wx[n + 256] = attn_w[2 * H_ + 256 + n];
    __syncthreads();

    const float* p = in + (size_t)b * T_ * N_ + n;
    float acc = 0.f;
#pragma unroll 8
    for (int t = 0; t < T_; ++t)
        acc = fmaf(p[(size_t)t * N_], wx[t], acc);

    red[n] = acc;
    __syncthreads();
    for (int s = 128; s > 0; s >>= 1) {
        if (n < s) red[n] = fmaxf(red[n], red[n + s]);
        __syncthreads();
    }
    float mx = red[0];
    __syncthreads();
    float e = expf(acc - mx);
    red[n] = e;
    __syncthreads();
    for (int s = 128; s > 0; s >>= 1) {
        if (n < s) red[n] += red[n + s];
        __syncthreads();
    }
    g_attn[b * N_ + n] = e / red[0];
    g_hbuf[0][b * N_ + n] = 0.f;
}

// ---------------- K2: weighted = attn * x -> out region 0 + bf16 hi/lo ---------
__global__ void k_weighted(const float* __restrict__ in, float* __restrict__ out) {
    int blk = blockIdx.x;            // b*T_ + t
    int b = blk >> 9;
    int t = blk & 511;
    int n = threadIdx.x;
    size_t idx = (size_t)blk * N_ + n;
    float w = g_attn[b * N_ + n] * in[idx];
    out[idx] = w;
    size_t m = (size_t)t * B_ + b;   // GEMM row index
    __nv_bfloat16 hi = __float2bfloat16(w);
    __nv_bfloat16 lo = __float2bfloat16(w - __bfloat162float(hi));
    g_Ahi[m * N_ + n] = hi;
    g_Alo[m * N_ + n] = lo;
}

// ---------------- K2b: W_ih -> bf16 hi/lo ----------------
__global__ void k_convB(const float* __restrict__ Wih) {
    int j = blockIdx.x;
    int k = threadIdx.x;
    float v = Wih[(size_t)j * N_ + k];
    __nv_bfloat16 hi = __float2bfloat16(v);
    __nv_bfloat16 lo = __float2bfloat16(v - __bfloat162float(hi));
    g_Bhi[j * N_ + k] = hi;
    g_Blo[j * N_ + k] = lo;
}

// ---------------- K3: mma.sync bf16 split GEMM, cp.async double-buffered -------
// (unchanged — proven at 517us)
#define TILE_BYTES 16384           // 128 x 64 bf16

__global__ void __launch_bounds__(256) k_gemm_mma(
        const float* __restrict__ b_ih, const float* __restrict__ b_hh) {
    __shared__ __align__(16) __nv_bfloat16 Sb[4 * 128 * 64];   // 64 KB
    __shared__ float bias_s[128];

    int tid = threadIdx.x;
    int wid = tid >> 5;
    int lane = tid & 31;
    int nt = blockIdx.x;             // 0..7  gate tile
    int mt = blockIdx.y;             // 0..1023 m tile
    int j0 = nt * 128;
    int wm = wid >> 2;               // 0..1
    int wn = wid & 3;                // 0..3

    if (tid < 128) bias_s[tid] = b_ih[j0 + tid] + b_hh[j0 + tid];

    uint32_t s_base = smem_to_u32(Sb);

    int st_r[4], st_sw[4];
#pragma unroll
    for (int it = 0; it < 4; ++it) {
        int idx = tid + it * 256;        // 0..1023
        int r = idx >> 3;
        int kg = idx & 7;
        st_r[it] = r * 32 + kg;
        st_sw[it] = r * 8 + (kg ^ (r & 7));
    }

    const __nv_bfloat16* a_srcs[3] = {g_Ahi, g_Alo, g_Ahi};
    const __nv_bfloat16* b_srcs[3] = {g_Bhi, g_Bhi, g_Blo};

#define ISSUE_CHUNK(ch) do { \
        int _term = (ch) >> 2; \
        int _kk0 = ((ch) & 3) * 64; \
        const char* _gA = (const char*)(a_srcs[_term] + (size_t)mt * 128 * N_ + _kk0); \
        const char* _gB = (const char*)(b_srcs[_term] + (size_t)j0 * N_ + _kk0); \
        uint32_t _sa = s_base + ((ch) & 1) * 2u * TILE_BYTES; \
        uint32_t _sb = _sa + TILE_BYTES; \
        _Pragma("unroll") \
        for (int _it = 0; _it < 4; ++_it) { \
            CP_ASYNC16(_sa + (uint32_t)st_sw[_it] * 16u, _gA + (size_t)st_r[_it] * 16); \
            CP_ASYNC16(_sb + (uint32_t)st_sw[_it] * 16u, _gB + (size_t)st_r[_it] * 16); \
        } \
        CP_COMMIT(); \
    } while (0)

    int a_r15 = lane & 15;
    int a_kh  = lane >> 4;
    int b_row = ((lane & 16) >> 1) + (lane & 7);
    int b_kh  = (lane >> 3) & 1;

    float acc[4][4][4];
#pragma unroll
    for (int i = 0; i < 4; ++i)
#pragma unroll
        for (int j = 0; j < 4; ++j)
#pragma unroll
            for (int q = 0; q < 4; ++q) acc[i][j][q] = 0.f;

    ISSUE_CHUNK(0);

    for (int ch = 0; ch < 12; ++ch) {
        if (ch + 1 < 12) {
            ISSUE_CHUNK(ch + 1);
            CP_WAIT1();
        } else {
            CP_WAIT0();
        }
        __syncthreads();

        uint32_t as_base = s_base + (ch & 1) * 2u * TILE_BYTES;
        uint32_t bs_base = as_base + TILE_BYTES;

#pragma unroll
        for (int ks = 0; ks < 4; ++ks) {
            uint32_t afr[4][4];
            uint32_t bfr[4][2];
#pragma unroll
            for (int tm = 0; tm < 4; ++tm) {
                int row = wm * 64 + tm * 16 + a_r15;
                int c = (2 * ks + a_kh) ^ (a_r15 & 7);
                uint32_t addr = as_base + (uint32_t)(row * 64 + c * 8) * 2u;
                LDM_X4(afr[tm][0], afr[tm][1], afr[tm][2], afr[tm][3], addr);
            }
#pragma unroll
            for (int tn2 = 0; tn2 < 2; ++tn2) {
                int row = wn * 32 + tn2 * 16 + b_row;
                int c = (2 * ks + b_kh) ^ (b_row & 7);
                uint32_t addr = bs_base + (uint32_t)(row * 64 + c * 8) * 2u;
                uint32_t r0, r1, r2, r3;
                LDM_X4(r0, r1, r2, r3, addr);
                bfr[tn2 * 2 + 0][0] = r0; bfr[tn2 * 2 + 0][1] = r1;
                bfr[tn2 * 2 + 1][0] = r2; bfr[tn2 * 2 + 1][1] = r3;
            }
#pragma unroll
            for (int tm = 0; tm < 4; ++tm)
#pragma unroll
                for (int tn = 0; tn < 4; ++tn)
                    MMA16816(acc[tm][tn], afr[tm], bfr[tn]);
        }
        __syncthreads();
    }

    int qr = lane >> 2;
    int qc = (lane & 3) * 2;
#pragma unroll
    for (int tm = 0; tm < 4; ++tm) {
#pragma unroll
        for (int tn = 0; tn < 4; ++tn) {
            int colt = wn * 32 + tn * 8 + qc;
            size_t m0 = (size_t)mt * 128 + wm * 64 + tm * 16 + qr;
            float bx = bias_s[colt], by = bias_s[colt + 1];
            float2 v0 = make_float2(acc[tm][tn][0] + bx, acc[tm][tn][1] + by);
            float2 v1 = make_float2(acc[tm][tn][2] + bx, acc[tm][tn][3] + by);
            *(float2*)(g_G1 + m0 * G_ + j0 + colt) = v0;
            *(float2*)(g_G1 + (m0 + 8) * G_ + j0 + colt) = v1;
        }
    }
}

// ---------------- K4: persistent recurrence, tensor-core inner GEMM ------------
// CTA = 32 batches x 16 hid (64 gate cols, order n = hid*4 + q).
// D[32 b][64 n] = h[32 b][256 k] @ W[64 n][256 k]^T via m16n8k16 bf16 split
// (3 terms: hi*hi + lo*hi + hi*lo, same as K3). W bf16 subtiles built once.
// h staged per step from g_hbuf [b][h] with fp32->bf16 hi/lo split.
// Group barrier: 16 CTAs sharing the batch tile, monotonic counters (proven R11).
// SMEM bytes: WHI 32K | WLO 32K | AHI 16K | ALO 16K | gbuf 8.7K
#define S_WHI 0
#define S_WLO 32768
#define S_AHI 65536
#define S_ALO 81920
#define S_GB  98304
#define S_TOT 107008

__global__ void __launch_bounds__(128, 1) k_recur(
        const float* __restrict__ Whh, float* __restrict__ out_enc) {
    extern __shared__ __align__(16) char smem[];
    uint32_t s_base = smem_to_u32(smem);
    float* gbuf = (float*)(smem + S_GB);      // [32][68] fp32 gate bounce

    int tid = threadIdx.x;            // 128 = 4 warps
    int lane = tid & 31;
    int wid = tid >> 5;
    int wm = wid & 1;                 // m half (16 batches)
    int wn = wid >> 1;                // n half (32 gate cols)
    int b0 = blockIdx.x * 32;
    int h0 = blockIdx.y * 16;
    int grp = blockIdx.x;

    // Build W bf16 hi/lo subtiles once. Subtile kc: [64 rows][64 k], row n = hid*4+q,
    // 128B rows, XOR-swizzled 16B granules (same scheme as K3 tiles).
    for (int idx = tid; idx < 4096; idx += 128) {
        int n = idx >> 6;             // 0..63
        int kq = idx & 63;            // float4 index along k
        int hid = n >> 2, q = n & 3;
        float4 v = *(const float4*)(Whh + (size_t)(q * H_ + h0 + hid) * N_ + kq * 4);
        uint2 hi, lo;
        split4(v, hi, lo);
        int kc = kq >> 4, kk = kq & 15, kg = kk >> 1, half = kk & 1;
        uint32_t off = (uint32_t)(kc * 8192 + n * 128 + ((kg ^ (n & 7)) << 4) + half * 8);
        *(uint2*)(smem + S_WHI + off) = hi;
        *(uint2*)(smem + S_WLO + off) = lo;
    }

    // ldmatrix lane precompute (identical to K3)
    int a_r15 = lane & 15;
    int a_kh  = lane >> 4;
    int b_row = ((lane & 16) >> 1) + (lane & 7);
    int b_kh  = (lane >> 3) & 1;

    // epilogue mapping: thread owns batch eb, hids [eh4*4, eh4*4+4)
    int eb  = tid & 31;
    int eh4 = tid >> 5;

    float creg[4] = {0.f, 0.f, 0.f, 0.f};
    __syncthreads();

    // G1 prefetch for t=0: g1s[q*4+j]
    float g1s[16];
#pragma unroll
    for (int q = 0; q < 4; ++q) {
        float4 v = __ldcg((const float4*)(g_G1 + ((size_t)(b0 + eb)) * G_ + q * 256 + h0 + eh4 * 4));
        g1s[q * 4 + 0] = v.x; g1s[q * 4 + 1] = v.y;
        g1s[q * 4 + 2] = v.z; g1s[q * 4 + 3] = v.w;
    }

    for (int t = 0; t < T_; ++t) {
        // stage h -> bf16 hi/lo A subtiles (kc: [32 rows b][64 k], 128B rows)
        const float4* gh4 = (const float4*)(g_hbuf[t & 1]) + (size_t)b0 * 64;
#pragma unroll
        for (int it = 0; it < 16; ++it) {
            int idx = tid + it * 128;     // 0..2047
            int b = idx >> 6;             // 0..31
            int kq = idx & 63;
            float4 v = __ldcg(gh4 + b * 64 + kq);
            uint2 hi, lo;
            split4(v, hi, lo);
            int kc = kq >> 4, kk = kq & 15, kg = kk >> 1, half = kk & 1;
            uint32_t off = (uint32_t)(kc * 4096 + b * 128 + ((kg ^ (b & 7)) << 4) + half * 8);
            *(uint2*)(smem + S_AHI + off) = hi;
            *(uint2*)(smem + S_ALO + off) = lo;
        }
        __syncthreads();

        // D = h @ W^T, 3-term bf16 split, warp tile m16 x n32
        float cfr[4][4];
#pragma unroll
        for (int tn = 0; tn < 4; ++tn)
#pragma unroll
            for (int q = 0; q < 4; ++q) cfr[tn][q] = 0.f;

#pragma unroll
        for (int kc = 0; kc < 4; ++kc) {
            uint32_t aHiB = s_base + S_AHI + kc * 4096;
            uint32_t aLoB = s_base + S_ALO + kc * 4096;
            uint32_t bHiB = s_base + S_WHI + kc * 8192;
            uint32_t bLoB = s_base + S_WLO + kc * 8192;
#pragma unroll
            for (int ks = 0; ks < 4; ++ks) {
                uint32_t ahi[4], alo[4], bhi[4][2], blo[4][2];
                int ac = (2 * ks + a_kh) ^ (a_r15 & 7);
                uint32_t aoff = (uint32_t)((wm * 16 + a_r15) * 128 + ac * 16);
                LDM_X4(ahi[0], ahi[1], ahi[2], ahi[3], aHiB + aoff);
                LDM_X4(alo[0], alo[1], alo[2], alo[3], aLoB + aoff);
#pragma unroll
                for (int tn2 = 0; tn2 < 2; ++tn2) {
                    int row = wn * 32 + tn2 * 16 + b_row;
                    int bc = (2 * ks + b_kh) ^ (b_row & 7);
                    uint32_t boff = (uint32_t)(row * 128 + bc * 16);
                    uint32_t r0, r1, r2, r3;
                    LDM_X4(r0, r1, r2, r3, bHiB + boff);
                    bhi[tn2 * 2 + 0][0] = r0; bhi[tn2 * 2 + 0][1] = r1;
                    bhi[tn2 * 2 + 1][0] = r2; bhi[tn2 * 2 + 1][1] = r3;
                    LDM_X4(r0, r1, r2, r3, bLoB + boff);
                    blo[tn2 * 2 + 0][0] = r0; blo[tn2 * 2 + 0][1] = r1;
                    blo[tn2 * 2 + 1][0] = r2; blo[tn2 * 2 + 1][1] = r3;
                }
#pragma unroll
                for (int tn = 0; tn < 4; ++tn) MMA16816(cfr[tn], ahi, bhi[tn]);
#pragma unroll
                for (int tn = 0; tn < 4; ++tn) MMA16816(cfr[tn], alo, bhi[tn]);
#pragma unroll
                for (int tn = 0; tn < 4; ++tn) MMA16816(cfr[tn], ahi, blo[tn]);
            }
        }

        // scatter c-frags to gate bounce buffer
        int qr = lane >> 2, qc = (lane & 3) * 2;
#pragma unroll
        for (int tn = 0; tn < 4; ++tn) {
            int col = wn * 32 + tn * 8 + qc;
            int r0 = wm * 16 + qr;
            *(float2*)&gbuf[r0 * 68 + col] = make_float2(cfr[tn][0], cfr[tn][1]);
            *(float2*)&gbuf[(r0 + 8) * 68 + col] = make_float2(cfr[tn][2], cfr[tn][3]);
        }
        __syncthreads();

        // LSTM epilogue: thread reads 16 contiguous gates (4 hid x 4 q)
        float ga[16];
#pragma unroll
        for (int j4 = 0; j4 < 4; ++j4) {
            float4 v = *(const float4*)&gbuf[eb * 68 + eh4 * 16 + j4 * 4];
            ga[j4 * 4 + 0] = v.x; ga[j4 * 4 + 1] = v.y;
            ga[j4 * 4 + 2] = v.z; ga[j4 * 4 + 3] = v.w;
        }
        float hn[4];
#pragma unroll
        for (int j = 0; j < 4; ++j) {
            float gi = ga[j * 4 + 0] + g1s[0 * 4 + j];
            float gf = ga[j * 4 + 1] + g1s[1 * 4 + j];
            float gg = ga[j * 4 + 2] + g1s[2 * 4 + j];
            float go = ga[j * 4 + 3] + g1s[3 * 4 + j];
            float cc = fmaf(sigf(gf), creg[j], sigf(gi) * tanhfast(gg));
            creg[j] = cc;
            hn[j] = sigf(go) * tanhfast(cc);
        }
        float4 hv = make_float4(hn[0], hn[1], hn[2], hn[3]);
        __stcg((float4*)(g_hbuf[(t + 1) & 1] + (size_t)(b0 + eb) * H_ + h0 + eh4 * 4), hv);
        *(float4*)(out_enc + ((size_t)(b0 + eb) * T_ + t) * H_ + h0 + eh4 * 4) = hv;

        if (t + 1 < T_) {
            // prefetch G1 for t+1 (loads fly during barrier)
#pragma unroll
            for (int q = 0; q < 4; ++q) {
                float4 v = __ldcg((const float4*)(g_G1 + ((size_t)(t + 1) * B_ + b0 + eb) * G_ + q * 256 + h0 + eh4 * 4));
                g1s[q * 4 + 0] = v.x; g1s[q * 4 + 1] = v.y;
                g1s[q * 4 + 2] = v.z; g1s[q * 4 + 3] = v.w;
            }
            // ---- group barrier (16 CTAs, monotonic counter — proven R11) ----
            __threadfence();
            __syncthreads();
            if (tid == 0) atomicAdd(&g_cnt_grp[grp * 32], 1u);
            unsigned target = (unsigned)(t + 1) * 16u;
            volatile unsigned* cp = &g_cnt_grp[grp * 32];
            while (*cp < target) { __nanosleep(32); }
            __threadfence();
        }
    }
}

// ---------------- launch ----------------
extern "C" void kernel_launch(void* const* d_in, const int* in_sizes, int n_in,
                              void* d_out, int out_size) {
    const float* input  = (const float*)d_in[0];
    const float* W_ih   = (const float*)d_in[1];
    const float* W_hh   = (const float*)d_in[2];
    const float* b_ih   = (const float*)d_in[3];
    const float* b_hh   = (const float*)d_in[4];
    const float* attn_w = (const float*)d_in[5];
    float* out = (float*)d_out;

    cudaFuncSetAttribute(k_recur, cudaFuncAttributeMaxDynamicSharedMemorySize, S_TOT);

    // K1: attention weights (+ zero h state, zero group counters)
    k_attn<<<B_, N_>>>(input, attn_w);
    // K2: weighted input -> output region 0 + bf16 hi/lo staging
    k_weighted<<<B_ * T_, N_>>>(input, out);
    // K2b: W_ih bf16 hi/lo
    k_convB<<<G_, N_>>>(W_ih);
    // K3: HMMA split-bf16 GEMM into g_G1, cp.async double-buffered
    dim3 g3(8, 1024);
    k_gemm_mma<<<g3, 256>>>(b_ih, b_hh);
    // K4: persistent recurrence -> output region 1 (tensor-core inner GEMM)
    dim3 g4(8, 16);
    k_recur<<<g4, 128, S_TOT>>>(W_hh, out + ENC_OFF);
}